// round 4
// baseline (speedup 1.0000x reference)
#include <cuda_runtime.h>
#include <math.h>
#include <stdint.h>

#define B_   4
#define S_   512
#define E_   768
#define H_   12
#define D_   64
#define FF_  3072
#define L_   12
#define NTOK (B_*S_)     // 2048
#define BH   (B_*H_)     // 48
#define E3_  (3*E_)      // 2304

#define SCALE_INV 0.03608439182435161f   // 1/sqrt(768), applied AFTER softmax

// ---------------- scratch (static __device__, no allocation) ----------------
__device__ float g_h[NTOK*E_];
__device__ float g_q[BH*S_*D_];
__device__ float g_k[BH*S_*D_];
__device__ float g_v[BH*S_*D_];
__device__ float g_att[(size_t)BH*S_*S_];
__device__ float g_merged[NTOK*E_];
__device__ float g_oproj[NTOK*E_];
__device__ float g_r1[NTOK*E_];
__device__ float g_f[NTOK*E_];
__device__ float g_ff[NTOK*FF_];
__device__ float g_f2[NTOK*E_];
__device__ float g_x[NTOK*E_];
// tf32-rounded weight copies
__device__ float g_Wqkv_t[(size_t)L_*E_*E3_];
__device__ float g_Wp_t[(size_t)L_*E_*E_];
__device__ float g_W1_t[(size_t)L_*E_*FF_];
__device__ float g_W2_t[(size_t)L_*FF_*E_];

// ---------------- helpers ----------------
__device__ __forceinline__ uint32_t f2tf32(float f) {
    uint32_t u;
    asm("cvt.rna.tf32.f32 %0, %1;" : "=r"(u) : "f"(f));
    return u;
}
__device__ __forceinline__ float f2tf32f(float f) { return __uint_as_float(f2tf32(f)); }

__device__ __forceinline__ void mma_tf32(float* c, const uint32_t* a, const uint32_t* b) {
    asm volatile(
        "mma.sync.aligned.m16n8k8.row.col.f32.tf32.tf32.f32 "
        "{%0,%1,%2,%3}, {%4,%5,%6,%7}, {%8,%9}, {%0,%1,%2,%3};"
        : "+f"(c[0]), "+f"(c[1]), "+f"(c[2]), "+f"(c[3])
        : "r"(a[0]), "r"(a[1]), "r"(a[2]), "r"(a[3]), "r"(b[0]), "r"(b[1]));
}

__device__ __forceinline__ void cp_async16(void* smem, const void* gmem) {
    uint32_t s = (uint32_t)__cvta_generic_to_shared(smem);
    asm volatile("cp.async.cg.shared.global [%0], [%1], 16;\n" :: "r"(s), "l"(gmem));
}
__device__ __forceinline__ void cp_commit() {
    asm volatile("cp.async.commit_group;\n");
}
template<int N> __device__ __forceinline__ void cp_wait() {
    asm volatile("cp.async.wait_group %0;\n" :: "n"(N));
}

__device__ __forceinline__ float gelu_exact(float x) {
    return 0.5f * x * (1.0f + erff(x * 0.7071067811865476f));
}

// ---------------- tensor-core tf32 GEMM, cp.async 3-stage ----------------
// C[M,N] = A[M,K] @ B (+bias). Inputs must already be tf32-rounded fp32.
// NTB=false: B [K,N] row-major; NTB=true: B [N,K] row-major (C = A@B^T).
// act: 0 plain; 1 gelu + tf32-round output; 2 qkv-split scatter; 3 merge-heads.
template<int BM, int BN, bool NTB, int WRM, int WRN>
__global__ void __launch_bounds__(WRM*WRN*32, 2) gemm_cp(
    const float* __restrict__ A, const float* __restrict__ Bm,
    const float* __restrict__ bias, float* __restrict__ C,
    int M, int N, int K,
    long long sA, long long sB, long long sC, int act,
    float* __restrict__ qp, float* __restrict__ kp, float* __restrict__ vp)
{
    constexpr int BK = 32;
    constexpr int STAGES = 3;
    constexpr int THREADS = WRM * WRN * 32;
    constexpr int WM = BM / WRM;
    constexpr int WN = BN / WRN;
    constexpr int MT = WM / 16;
    constexpr int NTL = WN / 8;
    constexpr int ASTR = BK + 4;                     // 36
    constexpr int BSTR = NTB ? (BK + 4) : (BN + 8);
    constexpr int BROWS = NTB ? BN : BK;
    constexpr int ASZ = BM * ASTR;
    constexpr int BSZ = BROWS * BSTR;
    constexpr int AC = BM * BK / 4 / THREADS;        // float4 chunks per thread (A)
    constexpr int BC = BN * BK / 4 / THREADS;        // (B)

    extern __shared__ uint32_t sm[];
    uint32_t* As = sm;                     // [STAGES][ASZ]
    uint32_t* Bs = sm + STAGES * ASZ;      // [STAGES][BSZ]

    A  += (long long)blockIdx.z * sA;
    Bm += (long long)blockIdx.z * sB;
    C  += (long long)blockIdx.z * sC;

    const int tid  = threadIdx.x;
    const int lane = tid & 31;
    const int warp = tid >> 5;
    const int wm = (warp % WRM) * WM;
    const int wn = (warp / WRM) * WN;
    const int bm = blockIdx.y * BM;
    const int bn = blockIdx.x * BN;

    const int niter = K / BK;

    float acc[MT][NTL][4] = {};

    auto issue = [&](int s) {
        int buf = s % STAGES;
        int k0 = s * BK;
        #pragma unroll
        for (int r = 0; r < AC; r++) {
            int f4 = tid + r * THREADS;
            int row = f4 / (BK / 4), c4 = f4 % (BK / 4);
            cp_async16(&As[buf * ASZ + row * ASTR + c4 * 4],
                       &A[(long long)(bm + row) * K + k0 + c4 * 4]);
        }
        #pragma unroll
        for (int r = 0; r < BC; r++) {
            int f4 = tid + r * THREADS;
            if (NTB) {
                int row = f4 / (BK / 4), c4 = f4 % (BK / 4);
                cp_async16(&Bs[buf * BSZ + row * BSTR + c4 * 4],
                           &Bm[(long long)(bn + row) * K + k0 + c4 * 4]);
            } else {
                int row = f4 / (BN / 4), c4 = f4 % (BN / 4);
                cp_async16(&Bs[buf * BSZ + row * BSTR + c4 * 4],
                           &Bm[(long long)(k0 + row) * N + bn + c4 * 4]);
            }
        }
    };

    auto compute = [&](int buf) {
        const uint32_t* Ab = &As[buf * ASZ];
        const uint32_t* Bb = &Bs[buf * BSZ];
        #pragma unroll
        for (int kk = 0; kk < 4; kk++) {
            uint32_t af[MT][4];
            {
                int r0 = wm + (lane >> 2);
                int c0 = kk * 8 + (lane & 3);
                #pragma unroll
                for (int i = 0; i < MT; i++) {
                    const uint32_t* p = &Ab[(r0 + i * 16) * ASTR + c0];
                    af[i][0] = p[0];
                    af[i][1] = p[8 * ASTR];
                    af[i][2] = p[4];
                    af[i][3] = p[8 * ASTR + 4];
                }
            }
            uint32_t bf[NTL][2];
            #pragma unroll
            for (int j = 0; j < NTL; j++) {
                if (NTB) {
                    const uint32_t* p = &Bb[(wn + j * 8 + (lane >> 2)) * BSTR
                                            + kk * 8 + (lane & 3)];
                    bf[j][0] = p[0];
                    bf[j][1] = p[4];
                } else {
                    const uint32_t* p = &Bb[(kk * 8 + (lane & 3)) * BSTR
                                            + wn + j * 8 + (lane >> 2)];
                    bf[j][0] = p[0];
                    bf[j][1] = p[4 * BSTR];
                }
            }
            #pragma unroll
            for (int i = 0; i < MT; i++)
                #pragma unroll
                for (int j = 0; j < NTL; j++)
                    mma_tf32(acc[i][j], af[i], bf[j]);
        }
    };

    // prologue: issue STAGES-1 stages
    #pragma unroll
    for (int s = 0; s < STAGES - 1; s++) {
        if (s < niter) issue(s);
        cp_commit();
    }
    // main loop
    for (int it = 0; it < niter; ++it) {
        cp_wait<STAGES - 2>();
        __syncthreads();
        int nxt = it + STAGES - 1;
        if (nxt < niter) issue(nxt);
        cp_commit();
        compute(it % STAGES);
    }

    // ---- epilogue ----
    const int z = blockIdx.z;
    #pragma unroll
    for (int i = 0; i < MT; i++) {
        #pragma unroll
        for (int j = 0; j < NTL; j++) {
            int row = bm + wm + i * 16 + (lane >> 2);
            int col = bn + wn + j * 8 + (lane & 3) * 2;
            float2 bv = make_float2(0.f, 0.f);
            if (bias) bv = *(const float2*)&bias[col];
            float o[2][2] = {{acc[i][j][0] + bv.x, acc[i][j][1] + bv.y},
                             {acc[i][j][2] + bv.x, acc[i][j][3] + bv.y}};
            if (act == 0) {
                *(float2*)&C[(long long)row * N + col]       = make_float2(o[0][0], o[0][1]);
                *(float2*)&C[(long long)(row + 8) * N + col] = make_float2(o[1][0], o[1][1]);
            } else if (act == 1) {
                *(float2*)&C[(long long)row * N + col] =
                    make_float2(f2tf32f(gelu_exact(o[0][0])), f2tf32f(gelu_exact(o[0][1])));
                *(float2*)&C[(long long)(row + 8) * N + col] =
                    make_float2(f2tf32f(gelu_exact(o[1][0])), f2tf32f(gelu_exact(o[1][1])));
            } else if (act == 2) {
                // qkv split: n -> (c = n%3 selects q/k/v, hd = n/3)
                #pragma unroll
                for (int r = 0; r < 2; r++) {
                    int rr = row + r * 8;
                    int b = rr >> 9, s = rr & 511;
                    #pragma unroll
                    for (int cc = 0; cc < 2; cc++) {
                        int n = col + cc;
                        int c = n % 3, hd = n / 3;
                        int h = hd >> 6, d = hd & 63;
                        long long idx = ((long long)(b * H_ + h) * S_ + s) * D_ + d;
                        float val = f2tf32f(o[r][cc]);
                        if (c == 0) qp[idx] = val;
                        else if (c == 1) kp[idx] = val;
                        else vp[idx] = val;
                    }
                }
            } else {
                // merge heads: z = b*H + h, write [b,s,h*64+d], tf32-rounded
                int b = z / H_, h = z % H_;
                #pragma unroll
                for (int r = 0; r < 2; r++) {
                    int rr = row + r * 8;
                    *(float2*)&C[((long long)(b * S_ + rr)) * E_ + h * D_ + col] =
                        make_float2(f2tf32f(o[r][0]), f2tf32f(o[r][1]));
                }
            }
        }
    }
}

// ---------------- reductions ----------------
__device__ __forceinline__ float block_reduce(float v, int op /*0 sum, 1 max*/) {
    __shared__ float sh[8];
    int lane = threadIdx.x & 31, wid = threadIdx.x >> 5;
    #pragma unroll
    for (int o = 16; o; o >>= 1) {
        float t = __shfl_xor_sync(0xffffffffu, v, o);
        v = op ? fmaxf(v, t) : (v + t);
    }
    if (lane == 0) sh[wid] = v;
    __syncthreads();
    if (wid == 0) {
        v = (lane < 8) ? sh[lane] : (op ? -INFINITY : 0.0f);
        #pragma unroll
        for (int o = 4; o; o >>= 1) {
            float t = __shfl_xor_sync(0xffffffffu, v, o);
            v = op ? fmaxf(v, t) : (v + t);
        }
        if (lane == 0) sh[0] = v;
    }
    __syncthreads();
    float r = sh[0];
    __syncthreads();
    return r;
}

// ---------------- LayerNorm (+ up to two residual adds, optional tf32 out) --
__global__ __launch_bounds__(256) void ln_kernel(
    const float* __restrict__ in, const float* __restrict__ g,
    const float* __restrict__ bb, const float* __restrict__ res1,
    const float* __restrict__ res2, float* __restrict__ out, int docvt)
{
    long long base = (long long)blockIdx.x * E_;
    int t = threadIdx.x;
    float v[3];
    #pragma unroll
    for (int i = 0; i < 3; i++) v[i] = in[base + t + i*256];
    float s  = v[0] + v[1] + v[2];
    float sq = v[0]*v[0] + v[1]*v[1] + v[2]*v[2];
    s  = block_reduce(s, 0);
    sq = block_reduce(sq, 0);
    float mean = s * (1.0f/E_);
    float var  = sq * (1.0f/E_) - mean*mean;
    float rstd = rsqrtf(var + 1e-5f);
    #pragma unroll
    for (int i = 0; i < 3; i++) {
        int c = t + i*256;
        float o = (v[i] - mean) * rstd * g[c] + bb[c];
        if (res1) o += res1[base + c];
        if (res2) o += res2[base + c];
        if (docvt) o = f2tf32f(o);
        out[base + c] = o;
    }
}

// ---------------- softmax rows of 512, * 1/sqrt(768), tf32 out -------------
__global__ __launch_bounds__(256) void softmax_div(float* __restrict__ att)
{
    float* p = att + (long long)blockIdx.x * S_;
    int t = threadIdx.x;
    float v0 = p[t], v1 = p[t + 256];
    float m = block_reduce(fmaxf(v0, v1), 1);
    v0 = expf(v0 - m);
    v1 = expf(v1 - m);
    float s = block_reduce(v0 + v1, 0);
    float inv = SCALE_INV / s;
    p[t]       = f2tf32f(v0 * inv);
    p[t + 256] = f2tf32f(v1 * inv);
}

// ---------------- weight tf32 pre-rounding ----------------
__global__ __launch_bounds__(256) void cvt_tf32_kernel(
    const float* __restrict__ in, float* __restrict__ out, long long n4)
{
    long long i = ((long long)blockIdx.x * 256 + threadIdx.x);
    if (i >= n4) return;
    float4 v = *(const float4*)&in[i * 4];
    v.x = f2tf32f(v.x); v.y = f2tf32f(v.y);
    v.z = f2tf32f(v.z); v.w = f2tf32f(v.w);
    *(float4*)&out[i * 4] = v;
}

// ---------------- host orchestration ----------------
#define SMEM_NN128 ((3*(128*36) + 3*(32*136)) * 4)   // 107520
#define SMEM_NT128 ((3*(128*36) + 3*(128*36)) * 4)   // 110592
#define SMEM_NN64  ((3*(128*36) + 3*(32*72))  * 4)   // 82944

extern "C" void kernel_launch(void* const* d_in, const int* in_sizes, int n_in,
                              void* d_out, int out_size)
{
    (void)in_sizes; (void)n_in; (void)out_size;

    const float* x_in  = (const float*)d_in[0];
    const float* Wqkv  = (const float*)d_in[1];
    const float* bqkv  = (const float*)d_in[2];
    const float* Wp    = (const float*)d_in[3];
    const float* bp    = (const float*)d_in[4];
    const float* W1    = (const float*)d_in[5];
    const float* b1    = (const float*)d_in[6];
    const float* W2    = (const float*)d_in[7];
    const float* b2    = (const float*)d_in[8];
    const float* g1    = (const float*)d_in[9];
    const float* be1   = (const float*)d_in[10];
    const float* g2    = (const float*)d_in[11];
    const float* be2   = (const float*)d_in[12];
    const float* g3    = (const float*)d_in[13];
    const float* be3   = (const float*)d_in[14];
    const float* g4    = (const float*)d_in[15];
    const float* be4   = (const float*)d_in[16];

    static bool attr_done = false;
    if (!attr_done) {
        cudaFuncSetAttribute(gemm_cp<128,128,false,2,2>,
                             cudaFuncAttributeMaxDynamicSharedMemorySize, SMEM_NN128);
        cudaFuncSetAttribute(gemm_cp<128,128,true,2,2>,
                             cudaFuncAttributeMaxDynamicSharedMemorySize, SMEM_NT128);
        cudaFuncSetAttribute(gemm_cp<128,64,false,2,2>,
                             cudaFuncAttributeMaxDynamicSharedMemorySize, SMEM_NN64);
        attr_done = true;
    }

    float *p_h, *p_q, *p_k, *p_v, *p_att, *p_merged, *p_oproj,
          *p_r1, *p_f, *p_ff, *p_f2, *p_x;
    float *w_qkv, *w_p, *w_1, *w_2;
    cudaGetSymbolAddress((void**)&p_h, g_h);
    cudaGetSymbolAddress((void**)&p_q, g_q);
    cudaGetSymbolAddress((void**)&p_k, g_k);
    cudaGetSymbolAddress((void**)&p_v, g_v);
    cudaGetSymbolAddress((void**)&p_att, g_att);
    cudaGetSymbolAddress((void**)&p_merged, g_merged);
    cudaGetSymbolAddress((void**)&p_oproj, g_oproj);
    cudaGetSymbolAddress((void**)&p_r1, g_r1);
    cudaGetSymbolAddress((void**)&p_f, g_f);
    cudaGetSymbolAddress((void**)&p_ff, g_ff);
    cudaGetSymbolAddress((void**)&p_f2, g_f2);
    cudaGetSymbolAddress((void**)&p_x, g_x);
    cudaGetSymbolAddress((void**)&w_qkv, g_Wqkv_t);
    cudaGetSymbolAddress((void**)&w_p, g_Wp_t);
    cudaGetSymbolAddress((void**)&w_1, g_W1_t);
    cudaGetSymbolAddress((void**)&w_2, g_W2_t);

    // pre-round all weights to tf32 (once per launch)
    {
        long long n;
        n = (long long)L_*E_*E3_ / 4;
        cvt_tf32_kernel<<<(unsigned)((n + 255) / 256), 256>>>(Wqkv, w_qkv, n);
        n = (long long)L_*E_*E_ / 4;
        cvt_tf32_kernel<<<(unsigned)((n + 255) / 256), 256>>>(Wp, w_p, n);
        n = (long long)L_*E_*FF_ / 4;
        cvt_tf32_kernel<<<(unsigned)((n + 255) / 256), 256>>>(W1, w_1, n);
        n = (long long)L_*FF_*E_ / 4;
        cvt_tf32_kernel<<<(unsigned)((n + 255) / 256), 256>>>(W2, w_2, n);
    }

    cudaMemcpyAsync(p_x, x_in, (size_t)NTOK * E_ * sizeof(float),
                    cudaMemcpyDeviceToDevice, 0);

    for (int l = 0; l < L_; ++l) {
        const float* Wqkv_l = w_qkv + (long long)l * E_ * E3_;
        const float* bqkv_l = bqkv + (long long)l * E3_;
        const float* Wp_l   = w_p  + (long long)l * E_ * E_;
        const float* bp_l   = bp   + (long long)l * E_;
        const float* W1_l   = w_1  + (long long)l * E_ * FF_;
        const float* b1_l   = b1   + (long long)l * FF_;
        const float* W2_l   = w_2  + (long long)l * FF_ * E_;
        const float* b2_l   = b2   + (long long)l * E_;
        const float* g1_l = g1 + (long long)l * E_, *be1_l = be1 + (long long)l * E_;
        const float* g2_l = g2 + (long long)l * E_, *be2_l = be2 + (long long)l * E_;
        const float* g3_l = g3 + (long long)l * E_, *be3_l = be3 + (long long)l * E_;
        const float* g4_l = g4 + (long long)l * E_, *be4_l = be4 + (long long)l * E_;

        // h = LN1(x), tf32-rounded
        ln_kernel<<<NTOK, 256>>>(p_x, g1_l, be1_l, nullptr, nullptr, p_h, 1);
        // qkv = h @ Wqkv + bqkv  -> fused split into q,k,v (tf32-rounded)
        gemm_cp<128,128,false,2,2><<<dim3(E3_/128, NTOK/128, 1), 128, SMEM_NN128>>>(
            p_h, Wqkv_l, bqkv_l, nullptr, NTOK, E3_, E_, 0, 0, 0, 2, p_q, p_k, p_v);
        // energy = Q @ K^T   (batched)
        gemm_cp<128,128,true,2,2><<<dim3(S_/128, S_/128, BH), 128, SMEM_NT128>>>(
            p_q, p_k, nullptr, p_att, S_, S_, D_,
            (long long)S_*D_, (long long)S_*D_, (long long)S_*S_, 0,
            nullptr, nullptr, nullptr);
        // att = softmax(energy) / sqrt(E), tf32-rounded
        softmax_div<<<BH * S_, 256>>>(p_att);
        // O = att @ V  -> fused merge-heads into p_merged (tf32-rounded)
        gemm_cp<128,64,false,2,2><<<dim3(1, S_/128, BH), 128, SMEM_NN64>>>(
            p_att, p_v, nullptr, p_merged, S_, D_, S_,
            (long long)S_*S_, (long long)S_*D_, 0, 3, nullptr, nullptr, nullptr);
        // oproj = merged @ Wp + bp
        gemm_cp<128,128,false,2,2><<<dim3(E_/128, NTOK/128, 1), 128, SMEM_NN128>>>(
            p_merged, Wp_l, bp_l, p_oproj, NTOK, E_, E_, 0, 0, 0, 0,
            nullptr, nullptr, nullptr);
        // r1 = LN2(oproj) + x
        ln_kernel<<<NTOK, 256>>>(p_oproj, g2_l, be2_l, p_x, nullptr, p_r1, 0);
        // f = LN3(r1), tf32-rounded
        ln_kernel<<<NTOK, 256>>>(p_r1, g3_l, be3_l, nullptr, nullptr, p_f, 1);
        // ff = gelu(f @ W1 + b1), tf32-rounded
        gemm_cp<128,128,false,2,2><<<dim3(FF_/128, NTOK/128, 1), 128, SMEM_NN128>>>(
            p_f, W1_l, b1_l, p_ff, NTOK, FF_, E_, 0, 0, 0, 1,
            nullptr, nullptr, nullptr);
        // f2 = ff @ W2 + b2
        gemm_cp<128,128,false,2,2><<<dim3(E_/128, NTOK/128, 1), 128, SMEM_NN128>>>(
            p_ff, W2_l, b2_l, p_f2, NTOK, E_, FF_, 0, 0, 0, 0,
            nullptr, nullptr, nullptr);
        // x = LN4(f2) + r1 + x
        ln_kernel<<<NTOK, 256>>>(p_f2, g4_l, be4_l, p_r1, p_x, p_x, 0);
    }

    cudaMemcpyAsync(d_out, p_x, (size_t)NTOK * E_ * sizeof(float),
                    cudaMemcpyDeviceToDevice, 0);
}

// round 5
// speedup vs baseline: 1.1396x; 1.1396x over previous
#include <cuda_runtime.h>
#include <math.h>
#include <stdint.h>

#define B_   4
#define S_   512
#define E_   768
#define H_   12
#define D_   64
#define FF_  3072
#define L_   12
#define NTOK (B_*S_)     // 2048
#define BH   (B_*H_)     // 48
#define E3_  (3*E_)      // 2304

#define SCALE_INV 0.03608439182435161f   // 1/sqrt(768), applied AFTER softmax

// ---------------- scratch (static __device__, no allocation) ----------------
__device__ float g_h[NTOK*E_];
__device__ float g_q[BH*S_*D_];
__device__ float g_k[BH*S_*D_];
__device__ float g_v[BH*S_*D_];
__device__ float g_merged[NTOK*E_];
__device__ float g_oproj[NTOK*E_];
__device__ float g_r1[NTOK*E_];
__device__ float g_f[NTOK*E_];
__device__ float g_ff[NTOK*FF_];
__device__ float g_f2[NTOK*E_];
__device__ float g_x[NTOK*E_];
// tf32-rounded weight copies
__device__ float g_Wqkv_t[(size_t)L_*E_*E3_];
__device__ float g_Wp_t[(size_t)L_*E_*E_];
__device__ float g_W1_t[(size_t)L_*E_*FF_];
__device__ float g_W2_t[(size_t)L_*FF_*E_];

// ---------------- helpers ----------------
__device__ __forceinline__ uint32_t f2tf32(float f) {
    uint32_t u;
    asm("cvt.rna.tf32.f32 %0, %1;" : "=r"(u) : "f"(f));
    return u;
}
__device__ __forceinline__ float f2tf32f(float f) { return __uint_as_float(f2tf32(f)); }

__device__ __forceinline__ void mma_tf32(float* c, const uint32_t* a, const uint32_t* b) {
    asm volatile(
        "mma.sync.aligned.m16n8k8.row.col.f32.tf32.tf32.f32 "
        "{%0,%1,%2,%3}, {%4,%5,%6,%7}, {%8,%9}, {%0,%1,%2,%3};"
        : "+f"(c[0]), "+f"(c[1]), "+f"(c[2]), "+f"(c[3])
        : "r"(a[0]), "r"(a[1]), "r"(a[2]), "r"(a[3]), "r"(b[0]), "r"(b[1]));
}

__device__ __forceinline__ void cp_async16(void* smem, const void* gmem) {
    uint32_t s = (uint32_t)__cvta_generic_to_shared(smem);
    asm volatile("cp.async.cg.shared.global [%0], [%1], 16;\n" :: "r"(s), "l"(gmem));
}
__device__ __forceinline__ void cp_commit() {
    asm volatile("cp.async.commit_group;\n");
}
template<int N> __device__ __forceinline__ void cp_wait() {
    asm volatile("cp.async.wait_group %0;\n" :: "n"(N));
}

__device__ __forceinline__ float gelu_exact(float x) {
    return 0.5f * x * (1.0f + erff(x * 0.7071067811865476f));
}

// ---------------- tensor-core tf32 GEMM, cp.async 3-stage (R3 config) -------
// C[M,N] = A[M,K] @ B (+bias). Inputs already tf32-rounded fp32. B [K,N] row-major.
// act: 0 plain; 1 gelu + tf32-round; 2 qkv-split scatter (tf32-round).
template<int BM, int BN, int WRM, int WRN>
__global__ void __launch_bounds__(WRM*WRN*32, 2) gemm_cp(
    const float* __restrict__ A, const float* __restrict__ Bm,
    const float* __restrict__ bias, float* __restrict__ C,
    int M, int N, int K, int act,
    float* __restrict__ qp, float* __restrict__ kp, float* __restrict__ vp)
{
    constexpr int BK = 32;
    constexpr int STAGES = 3;
    constexpr int THREADS = WRM * WRN * 32;
    constexpr int WM = BM / WRM;
    constexpr int WN = BN / WRN;
    constexpr int MT = WM / 16;
    constexpr int NTL = WN / 8;
    constexpr int ASTR = BK + 4;                     // 36
    constexpr int BSTR = BN + 8;                     // 136
    constexpr int ASZ = BM * ASTR;
    constexpr int BSZ = BK * BSTR;
    constexpr int AC = BM * BK / 4 / THREADS;
    constexpr int BC = BN * BK / 4 / THREADS;

    extern __shared__ uint32_t sm[];
    uint32_t* As = sm;
    uint32_t* Bs = sm + STAGES * ASZ;

    const int tid  = threadIdx.x;
    const int lane = tid & 31;
    const int warp = tid >> 5;
    const int wm = (warp % WRM) * WM;
    const int wn = (warp / WRM) * WN;
    const int bm = blockIdx.y * BM;
    const int bn = blockIdx.x * BN;

    const int niter = K / BK;

    float acc[MT][NTL][4] = {};

    auto issue = [&](int s) {
        int buf = s % STAGES;
        int k0 = s * BK;
        #pragma unroll
        for (int r = 0; r < AC; r++) {
            int f4 = tid + r * THREADS;
            int row = f4 / (BK / 4), c4 = f4 % (BK / 4);
            cp_async16(&As[buf * ASZ + row * ASTR + c4 * 4],
                       &A[(long long)(bm + row) * K + k0 + c4 * 4]);
        }
        #pragma unroll
        for (int r = 0; r < BC; r++) {
            int f4 = tid + r * THREADS;
            int row = f4 / (BN / 4), c4 = f4 % (BN / 4);
            cp_async16(&Bs[buf * BSZ + row * BSTR + c4 * 4],
                       &Bm[(long long)(k0 + row) * N + bn + c4 * 4]);
        }
    };

    auto compute = [&](int buf) {
        const uint32_t* Ab = &As[buf * ASZ];
        const uint32_t* Bb = &Bs[buf * BSZ];
        #pragma unroll
        for (int kk = 0; kk < 4; kk++) {
            uint32_t af[MT][4];
            {
                int r0 = wm + (lane >> 2);
                int c0 = kk * 8 + (lane & 3);
                #pragma unroll
                for (int i = 0; i < MT; i++) {
                    const uint32_t* p = &Ab[(r0 + i * 16) * ASTR + c0];
                    af[i][0] = p[0];
                    af[i][1] = p[8 * ASTR];
                    af[i][2] = p[4];
                    af[i][3] = p[8 * ASTR + 4];
                }
            }
            uint32_t bf[NTL][2];
            #pragma unroll
            for (int j = 0; j < NTL; j++) {
                const uint32_t* p = &Bb[(kk * 8 + (lane & 3)) * BSTR
                                        + wn + j * 8 + (lane >> 2)];
                bf[j][0] = p[0];
                bf[j][1] = p[4 * BSTR];
            }
            #pragma unroll
            for (int i = 0; i < MT; i++)
                #pragma unroll
                for (int j = 0; j < NTL; j++)
                    mma_tf32(acc[i][j], af[i], bf[j]);
        }
    };

    #pragma unroll
    for (int s = 0; s < STAGES - 1; s++) {
        if (s < niter) issue(s);
        cp_commit();
    }
    for (int it = 0; it < niter; ++it) {
        cp_wait<STAGES - 2>();
        __syncthreads();
        int nxt = it + STAGES - 1;
        if (nxt < niter) issue(nxt);
        cp_commit();
        compute(it % STAGES);
    }

    // ---- epilogue ----
    #pragma unroll
    for (int i = 0; i < MT; i++) {
        #pragma unroll
        for (int j = 0; j < NTL; j++) {
            int row = bm + wm + i * 16 + (lane >> 2);
            int col = bn + wn + j * 8 + (lane & 3) * 2;
            float2 bv = make_float2(0.f, 0.f);
            if (bias) bv = *(const float2*)&bias[col];
            float o[2][2] = {{acc[i][j][0] + bv.x, acc[i][j][1] + bv.y},
                             {acc[i][j][2] + bv.x, acc[i][j][3] + bv.y}};
            if (act == 0) {
                *(float2*)&C[(long long)row * N + col]       = make_float2(o[0][0], o[0][1]);
                *(float2*)&C[(long long)(row + 8) * N + col] = make_float2(o[1][0], o[1][1]);
            } else if (act == 1) {
                *(float2*)&C[(long long)row * N + col] =
                    make_float2(f2tf32f(gelu_exact(o[0][0])), f2tf32f(gelu_exact(o[0][1])));
                *(float2*)&C[(long long)(row + 8) * N + col] =
                    make_float2(f2tf32f(gelu_exact(o[1][0])), f2tf32f(gelu_exact(o[1][1])));
            } else {
                // qkv split: n -> (c = n%3 selects q/k/v, hd = n/3)
                #pragma unroll
                for (int r = 0; r < 2; r++) {
                    int rr = row + r * 8;
                    int b = rr >> 9, s = rr & 511;
                    #pragma unroll
                    for (int cc = 0; cc < 2; cc++) {
                        int n = col + cc;
                        int c = n % 3, hd = n / 3;
                        int h = hd >> 6, d = hd & 63;
                        long long idx = ((long long)(b * H_ + h) * S_ + s) * D_ + d;
                        float val = f2tf32f(o[r][cc]);
                        if (c == 0) qp[idx] = val;
                        else if (c == 1) kp[idx] = val;
                        else vp[idx] = val;
                    }
                }
            }
        }
    }
}

// ---------------- fused attention: S=QK^T, softmax, O=PV, merge -------------
// CTA: 64 query rows of one (b,h). smem: S 64x516, Q 64x68, KV 2x(128x72).
#define FA_OFF_Q  33024
#define FA_OFF_K0 37376
#define FA_OFF_K1 46592
#define FA_SMEM   ((46592 + 9216) * 4)      // 223232 bytes

__global__ void __launch_bounds__(256, 1) flash_kernel(
    const float* __restrict__ q, const float* __restrict__ k,
    const float* __restrict__ v, float* __restrict__ merged)
{
    extern __shared__ float fs[];
    float* Ssm = fs;                 // stride 516
    float* Qs  = fs + FA_OFF_Q;      // stride 68
    float* KVa = fs + FA_OFF_K0;     // K stride 68 / V stride 72
    float* KVb = fs + FA_OFF_K1;

    const int tid = threadIdx.x, lane = tid & 31, warp = tid >> 5;
    const int z = blockIdx.y;                 // b*H + h
    const int q0 = blockIdx.x * 64;
    const float* qg = q + (long long)z * S_ * D_ + (long long)q0 * D_;
    const float* kg = k + (long long)z * S_ * D_;
    const float* vg = v + (long long)z * S_ * D_;

    // load Q (64x64) and K0 (128x64)
    #pragma unroll
    for (int r = 0; r < 4; r++) {
        int chunk = tid + r * 256;
        int row = chunk >> 4, c4 = (chunk & 15) * 4;
        cp_async16(&Qs[row * 68 + c4], &qg[row * 64 + c4]);
    }
    #pragma unroll
    for (int r = 0; r < 8; r++) {
        int chunk = tid + r * 256;
        int row = chunk >> 4, c4 = (chunk & 15) * 4;
        cp_async16(&KVa[row * 68 + c4], &kg[row * 64 + c4]);
    }
    cp_commit();

    const int wm = (warp & 1) * 32;           // 2 row-warps
    const int wn1 = (warp >> 1) * 32;         // 4 col-warps (pass 1)

    // ---- pass 1: S = Q @ K^T ----
    for (int j = 0; j < 4; j++) {
        cp_wait<0>();
        __syncthreads();
        if (j < 3) {
            float* dst = ((j + 1) & 1) ? KVb : KVa;
            const float* src = kg + (long long)(j + 1) * 128 * 64;
            #pragma unroll
            for (int r = 0; r < 8; r++) {
                int chunk = tid + r * 256;
                int row = chunk >> 4, c4 = (chunk & 15) * 4;
                cp_async16(&dst[row * 68 + c4], &src[row * 64 + c4]);
            }
            cp_commit();
        }
        const float* Kb = (j & 1) ? KVb : KVa;
        float acc[2][4][4] = {};
        #pragma unroll
        for (int kk = 0; kk < 8; kk++) {
            int c0 = kk * 8 + (lane & 3);
            uint32_t af[2][4];
            #pragma unroll
            for (int i = 0; i < 2; i++) {
                const uint32_t* p = (const uint32_t*)&Qs[(wm + i * 16 + (lane >> 2)) * 68 + c0];
                af[i][0] = p[0]; af[i][1] = p[8 * 68];
                af[i][2] = p[4]; af[i][3] = p[8 * 68 + 4];
            }
            uint32_t bf[4][2];
            #pragma unroll
            for (int jj = 0; jj < 4; jj++) {
                const uint32_t* p = (const uint32_t*)&Kb[(wn1 + jj * 8 + (lane >> 2)) * 68 + c0];
                bf[jj][0] = p[0]; bf[jj][1] = p[4];
            }
            #pragma unroll
            for (int i = 0; i < 2; i++)
                #pragma unroll
                for (int jj = 0; jj < 4; jj++)
                    mma_tf32(acc[i][jj], af[i], bf[jj]);
        }
        #pragma unroll
        for (int i = 0; i < 2; i++) {
            #pragma unroll
            for (int jj = 0; jj < 4; jj++) {
                int r = wm + i * 16 + (lane >> 2);
                int col = j * 128 + wn1 + jj * 8 + (lane & 3) * 2;
                *(float2*)&Ssm[r * 516 + col]       = make_float2(acc[i][jj][0], acc[i][jj][1]);
                *(float2*)&Ssm[(r + 8) * 516 + col] = make_float2(acc[i][jj][2], acc[i][jj][3]);
            }
        }
    }
    // preload V0 into KVa (KVa held K2, consumed at j=2; safe)
    #pragma unroll
    for (int r = 0; r < 8; r++) {
        int chunk = tid + r * 256;
        int row = chunk >> 4, c4 = (chunk & 15) * 4;
        cp_async16(&KVa[row * 72 + c4], &vg[row * 64 + c4]);
    }
    cp_commit();
    __syncthreads();   // Ssm complete

    // ---- pass 2: softmax rows, *1/sqrt(768), tf32-round ----
    for (int rr = 0; rr < 8; rr++) {
        float* p = &Ssm[(warp * 8 + rr) * 516];
        float vals[16];
        float m = -INFINITY;
        #pragma unroll
        for (int i = 0; i < 16; i++) { vals[i] = p[lane + 32 * i]; m = fmaxf(m, vals[i]); }
        #pragma unroll
        for (int o = 16; o; o >>= 1) m = fmaxf(m, __shfl_xor_sync(0xffffffffu, m, o));
        float s = 0.f;
        #pragma unroll
        for (int i = 0; i < 16; i++) { vals[i] = expf(vals[i] - m); s += vals[i]; }
        #pragma unroll
        for (int o = 16; o; o >>= 1) s += __shfl_xor_sync(0xffffffffu, s, o);
        float inv = SCALE_INV / s;
        #pragma unroll
        for (int i = 0; i < 16; i++) p[lane + 32 * i] = f2tf32f(vals[i] * inv);
    }
    __syncthreads();

    // ---- pass 3: O = P @ V ----
    const int wn3 = (warp >> 1) * 16;        // 4 col-warps x 16 = 64
    float acco[2][2][4] = {};
    for (int j = 0; j < 4; j++) {
        cp_wait<0>();
        __syncthreads();
        if (j < 3) {
            float* dst = ((j + 1) & 1) ? KVb : KVa;
            const float* src = vg + (long long)(j + 1) * 128 * 64;
            #pragma unroll
            for (int r = 0; r < 8; r++) {
                int chunk = tid + r * 256;
                int row = chunk >> 4, c4 = (chunk & 15) * 4;
                cp_async16(&dst[row * 72 + c4], &src[row * 64 + c4]);
            }
            cp_commit();
        }
        const float* Vb = (j & 1) ? KVb : KVa;
        #pragma unroll
        for (int kk = 0; kk < 16; kk++) {
            int c0 = j * 128 + kk * 8 + (lane & 3);
            uint32_t af[2][4];
            #pragma unroll
            for (int i = 0; i < 2; i++) {
                const uint32_t* p = (const uint32_t*)&Ssm[(wm + i * 16 + (lane >> 2)) * 516 + c0];
                af[i][0] = p[0]; af[i][1] = p[8 * 516];
                af[i][2] = p[4]; af[i][3] = p[8 * 516 + 4];
            }
            uint32_t bf[2][2];
            #pragma unroll
            for (int jj = 0; jj < 2; jj++) {
                const uint32_t* p = (const uint32_t*)&Vb[(kk * 8 + (lane & 3)) * 72
                                                        + wn3 + jj * 8 + (lane >> 2)];
                bf[jj][0] = p[0]; bf[jj][1] = p[4 * 72];
            }
            #pragma unroll
            for (int i = 0; i < 2; i++)
                #pragma unroll
                for (int jj = 0; jj < 2; jj++)
                    mma_tf32(acco[i][jj], af[i], bf[jj]);
        }
    }

    // ---- epilogue: merged[b, s, h*64 + d], tf32-rounded ----
    const int b = z / H_, h = z % H_;
    #pragma unroll
    for (int i = 0; i < 2; i++) {
        #pragma unroll
        for (int jj = 0; jj < 2; jj++) {
            int r = wm + i * 16 + (lane >> 2);
            int col = wn3 + jj * 8 + (lane & 3) * 2;
            long long s0 = b * S_ + q0 + r;
            *(float2*)&merged[s0 * E_ + h * 64 + col] =
                make_float2(f2tf32f(acco[i][jj][0]), f2tf32f(acco[i][jj][1]));
            *(float2*)&merged[(s0 + 8) * E_ + h * 64 + col] =
                make_float2(f2tf32f(acco[i][jj][2]), f2tf32f(acco[i][jj][3]));
        }
    }
}

// ---------------- reductions ----------------
__device__ __forceinline__ float block_reduce(float v) {
    __shared__ float sh[8];
    int lane = threadIdx.x & 31, wid = threadIdx.x >> 5;
    #pragma unroll
    for (int o = 16; o; o >>= 1) v += __shfl_xor_sync(0xffffffffu, v, o);
    if (lane == 0) sh[wid] = v;
    __syncthreads();
    if (wid == 0) {
        v = (lane < 8) ? sh[lane] : 0.0f;
        #pragma unroll
        for (int o = 4; o; o >>= 1) v += __shfl_xor_sync(0xffffffffu, v, o);
        if (lane == 0) sh[0] = v;
    }
    __syncthreads();
    float r = sh[0];
    __syncthreads();
    return r;
}

// ---------------- LN (standalone, tf32 out) ----------------
__global__ __launch_bounds__(256) void ln_kernel(
    const float* __restrict__ in, const float* __restrict__ g,
    const float* __restrict__ bb, float* __restrict__ out)
{
    long long base = (long long)blockIdx.x * E_;
    int t = threadIdx.x;
    float v[3];
    #pragma unroll
    for (int i = 0; i < 3; i++) v[i] = in[base + t + i*256];
    float s  = block_reduce(v[0] + v[1] + v[2]);
    float sq = block_reduce(v[0]*v[0] + v[1]*v[1] + v[2]*v[2]);
    float mean = s * (1.0f/E_);
    float rstd = rsqrtf(sq * (1.0f/E_) - mean*mean + 1e-5f);
    #pragma unroll
    for (int i = 0; i < 3; i++) {
        int c = t + i*256;
        out[base + c] = f2tf32f((v[i] - mean) * rstd * g[c] + bb[c]);
    }
}

// ---------------- fused LN2(+x)->r1 then LN3->f(tf32) ----------------
__global__ __launch_bounds__(256) void ln2_ln3_kernel(
    const float* __restrict__ oproj, const float* __restrict__ x,
    const float* __restrict__ g2, const float* __restrict__ b2,
    const float* __restrict__ g3, const float* __restrict__ b3,
    float* __restrict__ r1, float* __restrict__ f)
{
    long long base = (long long)blockIdx.x * E_;
    int t = threadIdx.x;
    float v[3];
    #pragma unroll
    for (int i = 0; i < 3; i++) v[i] = oproj[base + t + i*256];
    float s  = block_reduce(v[0] + v[1] + v[2]);
    float sq = block_reduce(v[0]*v[0] + v[1]*v[1] + v[2]*v[2]);
    float mean = s * (1.0f/E_);
    float rstd = rsqrtf(sq * (1.0f/E_) - mean*mean + 1e-5f);
    #pragma unroll
    for (int i = 0; i < 3; i++) {
        int c = t + i*256;
        v[i] = (v[i] - mean) * rstd * g2[c] + b2[c] + x[base + c];
        r1[base + c] = v[i];
    }
    float s2  = block_reduce(v[0] + v[1] + v[2]);
    float sq2 = block_reduce(v[0]*v[0] + v[1]*v[1] + v[2]*v[2]);
    float mean2 = s2 * (1.0f/E_);
    float rstd2 = rsqrtf(sq2 * (1.0f/E_) - mean2*mean2 + 1e-5f);
    #pragma unroll
    for (int i = 0; i < 3; i++) {
        int c = t + i*256;
        f[base + c] = f2tf32f((v[i] - mean2) * rstd2 * g3[c] + b3[c]);
    }
}

// ---------------- fused LN4(+r1+x)->x then LN1(next)->h(tf32) ----------------
__global__ __launch_bounds__(256) void ln4_ln1_kernel(
    const float* __restrict__ f2, const float* __restrict__ r1,
    const float* __restrict__ x,
    const float* __restrict__ g4, const float* __restrict__ b4,
    const float* __restrict__ g1, const float* __restrict__ b1,
    float* __restrict__ xout, float* __restrict__ hout)
{
    long long base = (long long)blockIdx.x * E_;
    int t = threadIdx.x;
    float v[3];
    #pragma unroll
    for (int i = 0; i < 3; i++) v[i] = f2[base + t + i*256];
    float s  = block_reduce(v[0] + v[1] + v[2]);
    float sq = block_reduce(v[0]*v[0] + v[1]*v[1] + v[2]*v[2]);
    float mean = s * (1.0f/E_);
    float rstd = rsqrtf(sq * (1.0f/E_) - mean*mean + 1e-5f);
    #pragma unroll
    for (int i = 0; i < 3; i++) {
        int c = t + i*256;
        v[i] = (v[i] - mean) * rstd * g4[c] + b4[c] + r1[base + c] + x[base + c];
        xout[base + c] = v[i];
    }
    if (g1 == nullptr) return;
    float s2  = block_reduce(v[0] + v[1] + v[2]);
    float sq2 = block_reduce(v[0]*v[0] + v[1]*v[1] + v[2]*v[2]);
    float mean2 = s2 * (1.0f/E_);
    float rstd2 = rsqrtf(sq2 * (1.0f/E_) - mean2*mean2 + 1e-5f);
    #pragma unroll
    for (int i = 0; i < 3; i++) {
        int c = t + i*256;
        hout[base + c] = f2tf32f((v[i] - mean2) * rstd2 * g1[c] + b1[c]);
    }
}

// ---------------- weight tf32 pre-rounding ----------------
__global__ __launch_bounds__(256) void cvt_tf32_kernel(
    const float* __restrict__ in, float* __restrict__ out, long long n4)
{
    long long i = ((long long)blockIdx.x * 256 + threadIdx.x);
    if (i >= n4) return;
    float4 v = *(const float4*)&in[i * 4];
    v.x = f2tf32f(v.x); v.y = f2tf32f(v.y);
    v.z = f2tf32f(v.z); v.w = f2tf32f(v.w);
    *(float4*)&out[i * 4] = v;
}

// ---------------- host orchestration ----------------
#define SMEM_NN128 ((3*(128*36) + 3*(32*136)) * 4)   // 107520

extern "C" void kernel_launch(void* const* d_in, const int* in_sizes, int n_in,
                              void* d_out, int out_size)
{
    (void)in_sizes; (void)n_in; (void)out_size;

    const float* x_in  = (const float*)d_in[0];
    const float* Wqkv  = (const float*)d_in[1];
    const float* bqkv  = (const float*)d_in[2];
    const float* Wp    = (const float*)d_in[3];
    const float* bp    = (const float*)d_in[4];
    const float* W1    = (const float*)d_in[5];
    const float* b1    = (const float*)d_in[6];
    const float* W2    = (const float*)d_in[7];
    const float* b2    = (const float*)d_in[8];
    const float* g1    = (const float*)d_in[9];
    const float* be1   = (const float*)d_in[10];
    const float* g2    = (const float*)d_in[11];
    const float* be2   = (const float*)d_in[12];
    const float* g3    = (const float*)d_in[13];
    const float* be3   = (const float*)d_in[14];
    const float* g4    = (const float*)d_in[15];
    const float* be4   = (const float*)d_in[16];

    static bool attr_done = false;
    if (!attr_done) {
        cudaFuncSetAttribute(gemm_cp<128,128,2,4>,
                             cudaFuncAttributeMaxDynamicSharedMemorySize, SMEM_NN128);
        cudaFuncSetAttribute(flash_kernel,
                             cudaFuncAttributeMaxDynamicSharedMemorySize, FA_SMEM);
        attr_done = true;
    }

    float *p_h, *p_q, *p_k, *p_v, *p_merged, *p_oproj,
          *p_r1, *p_f, *p_ff, *p_f2, *p_x;
    float *w_qkv, *w_p, *w_1, *w_2;
    cudaGetSymbolAddress((void**)&p_h, g_h);
    cudaGetSymbolAddress((void**)&p_q, g_q);
    cudaGetSymbolAddress((void**)&p_k, g_k);
    cudaGetSymbolAddress((void**)&p_v, g_v);
    cudaGetSymbolAddress((void**)&p_merged, g_merged);
    cudaGetSymbolAddress((void**)&p_oproj, g_oproj);
    cudaGetSymbolAddress((void**)&p_r1, g_r1);
    cudaGetSymbolAddress((void**)&p_f, g_f);
    cudaGetSymbolAddress((void**)&p_ff, g_ff);
    cudaGetSymbolAddress((void**)&p_f2, g_f2);
    cudaGetSymbolAddress((void**)&p_x, g_x);
    cudaGetSymbolAddress((void**)&w_qkv, g_Wqkv_t);
    cudaGetSymbolAddress((void**)&w_p, g_Wp_t);
    cudaGetSymbolAddress((void**)&w_1, g_W1_t);
    cudaGetSymbolAddress((void**)&w_2, g_W2_t);

    // pre-round all weights to tf32 (once per launch)
    {
        long long n;
        n = (long long)L_*E_*E3_ / 4;
        cvt_tf32_kernel<<<(unsigned)((n + 255) / 256), 256>>>(Wqkv, w_qkv, n);
        n = (long long)L_*E_*E_ / 4;
        cvt_tf32_kernel<<<(unsigned)((n + 255) / 256), 256>>>(Wp, w_p, n);
        n = (long long)L_*E_*FF_ / 4;
        cvt_tf32_kernel<<<(unsigned)((n + 255) / 256), 256>>>(W1, w_1, n);
        n = (long long)L_*FF_*E_ / 4;
        cvt_tf32_kernel<<<(unsigned)((n + 255) / 256), 256>>>(W2, w_2, n);
    }

    cudaMemcpyAsync(p_x, x_in, (size_t)NTOK * E_ * sizeof(float),
                    cudaMemcpyDeviceToDevice, 0);

    // h = LN1_0(x)
    ln_kernel<<<NTOK, 256>>>(p_x, g1, be1, p_h);

    for (int l = 0; l < L_; ++l) {
        const float* Wqkv_l = w_qkv + (long long)l * E_ * E3_;
        const float* bqkv_l = bqkv + (long long)l * E3_;
        const float* Wp_l   = w_p  + (long long)l * E_ * E_;
        const float* bp_l   = bp   + (long long)l * E_;
        const float* W1_l   = w_1  + (long long)l * E_ * FF_;
        const float* b1_l   = b1   + (long long)l * FF_;
        const float* W2_l   = w_2  + (long long)l * FF_ * E_;
        const float* b2_l   = b2   + (long long)l * E_;
        const float* g2_l = g2 + (long long)l * E_, *be2_l = be2 + (long long)l * E_;
        const float* g3_l = g3 + (long long)l * E_, *be3_l = be3 + (long long)l * E_;
        const float* g4_l = g4 + (long long)l * E_, *be4_l = be4 + (long long)l * E_;

        // qkv = h @ Wqkv + bqkv  -> split q,k,v (tf32)
        gemm_cp<128,128,2,4><<<dim3(E3_/128, NTOK/128), 256, SMEM_NN128>>>(
            p_h, Wqkv_l, bqkv_l, nullptr, NTOK, E3_, E_, 2, p_q, p_k, p_v);
        // fused attention -> merged (tf32)
        flash_kernel<<<dim3(S_/64, BH), 256, FA_SMEM>>>(p_q, p_k, p_v, p_merged);
        // oproj = merged @ Wp + bp
        gemm_cp<128,128,2,4><<<dim3(E_/128, NTOK/128), 256, SMEM_NN128>>>(
            p_merged, Wp_l, bp_l, p_oproj, NTOK, E_, E_, 0, nullptr, nullptr, nullptr);
        // r1 = LN2(oproj) + x ; f = LN3(r1) (tf32)
        ln2_ln3_kernel<<<NTOK, 256>>>(p_oproj, p_x, g2_l, be2_l, g3_l, be3_l, p_r1, p_f);
        // ff = gelu(f @ W1 + b1) (tf32)
        gemm_cp<128,128,2,4><<<dim3(FF_/128, NTOK/128), 256, SMEM_NN128>>>(
            p_f, W1_l, b1_l, p_ff, NTOK, FF_, E_, 1, nullptr, nullptr, nullptr);
        // f2 = ff @ W2 + b2
        gemm_cp<128,128,2,4><<<dim3(E_/128, NTOK/128), 256, SMEM_NN128>>>(
            p_ff, W2_l, b2_l, p_f2, NTOK, E_, FF_, 0, nullptr, nullptr, nullptr);
        // x = LN4(f2) + r1 + x ; h = LN1_{l+1}(x) (tf32)
        const float* g1n  = (l + 1 < L_) ? g1  + (long long)(l + 1) * E_ : nullptr;
        const float* be1n = (l + 1 < L_) ? be1 + (long long)(l + 1) * E_ : nullptr;
        ln4_ln1_kernel<<<NTOK, 256>>>(p_f2, p_r1, p_x, g4_l, be4_l, g1n, be1n, p_x, p_h);
    }

    cudaMemcpyAsync(d_out, p_x, (size_t)NTOK * E_ * sizeof(float),
                    cudaMemcpyDeviceToDevice, 0);
}

// round 8
// speedup vs baseline: 1.5898x; 1.3950x over previous
#include <cuda_runtime.h>
#include <cuda_fp16.h>
#include <math.h>
#include <stdint.h>

#define B_   4
#define S_   512
#define E_   768
#define H_   12
#define D_   64
#define FF_  3072
#define L_   12
#define NTOK (B_*S_)     // 2048
#define BH   (B_*H_)     // 48
#define E3_  (3*E_)      // 2304

#define SCALE_INV 0.03608439182435161f   // 1/sqrt(768), applied AFTER softmax

// ---------------- scratch (static __device__, no allocation) ----------------
__device__ __half g_h[NTOK*E_];
__device__ float  g_q[BH*S_*D_];
__device__ float  g_k[BH*S_*D_];
__device__ float  g_v[BH*S_*D_];
__device__ __half g_merged[NTOK*E_];
__device__ float  g_oproj[NTOK*E_];
__device__ float  g_r1[NTOK*E_];
__device__ __half g_f[NTOK*E_];
__device__ __half g_ff[NTOK*FF_];
__device__ float  g_f2[NTOK*E_];
__device__ float  g_x[NTOK*E_];
// fp16 + transposed weight copies ([N][K] K-major per layer)
__device__ __half g_Wqkv_t[(size_t)L_*E_*E3_];
__device__ __half g_Wp_t[(size_t)L_*E_*E_];
__device__ __half g_W1_t[(size_t)L_*E_*FF_];
__device__ __half g_W2_t[(size_t)L_*FF_*E_];

// ---------------- helpers ----------------
__device__ __forceinline__ uint32_t f2tf32(float f) {
    uint32_t u;
    asm("cvt.rna.tf32.f32 %0, %1;" : "=r"(u) : "f"(f));
    return u;
}
__device__ __forceinline__ float f2tf32f(float f) { return __uint_as_float(f2tf32(f)); }

__device__ __forceinline__ void mma_tf32(float* c, const uint32_t* a, const uint32_t* b) {
    asm volatile(
        "mma.sync.aligned.m16n8k8.row.col.f32.tf32.tf32.f32 "
        "{%0,%1,%2,%3}, {%4,%5,%6,%7}, {%8,%9}, {%0,%1,%2,%3};"
        : "+f"(c[0]), "+f"(c[1]), "+f"(c[2]), "+f"(c[3])
        : "r"(a[0]), "r"(a[1]), "r"(a[2]), "r"(a[3]), "r"(b[0]), "r"(b[1]));
}

__device__ __forceinline__ void mma_f16(float* c, const uint32_t* a, const uint32_t* b) {
    asm volatile(
        "mma.sync.aligned.m16n8k16.row.col.f32.f16.f16.f32 "
        "{%0,%1,%2,%3}, {%4,%5,%6,%7}, {%8,%9}, {%0,%1,%2,%3};"
        : "+f"(c[0]), "+f"(c[1]), "+f"(c[2]), "+f"(c[3])
        : "r"(a[0]), "r"(a[1]), "r"(a[2]), "r"(a[3]), "r"(b[0]), "r"(b[1]));
}

__device__ __forceinline__ void cp_async16(void* smem, const void* gmem) {
    uint32_t s = (uint32_t)__cvta_generic_to_shared(smem);
    asm volatile("cp.async.cg.shared.global [%0], [%1], 16;\n" :: "r"(s), "l"(gmem));
}
__device__ __forceinline__ void cp_commit() {
    asm volatile("cp.async.commit_group;\n");
}
template<int N> __device__ __forceinline__ void cp_wait() {
    asm volatile("cp.async.wait_group %0;\n" :: "n"(N));
}

__device__ __forceinline__ float gelu_exact(float x) {
    return 0.5f * x * (1.0f + erff(x * 0.7071067811865476f));
}

// ---------------- fp16 tensor-core GEMM, cp.async 3-stage -------------------
// C = A[M,K](half) @ Bt[N,K](half, pre-transposed) + bias(f32).
// smem: A [m][k] stride 40 halves; B [n][k] stride 40 halves. BK=32.
// ACT: 0 plain f32 out; 1 gelu -> half out; 2 qkv-split scatter f32 (tf32-rounded).
#define GH_STAGE 20480                       // 10240 A + 10240 B
#define GH_SMEM  (3 * GH_STAGE)              // 61440

template<int ACT>
__global__ void __launch_bounds__(256, 2) gemm_h(
    const __half* __restrict__ A, const __half* __restrict__ Bt,
    const float* __restrict__ bias, void* __restrict__ Cout,
    int M, int N, int K,
    float* __restrict__ qp, float* __restrict__ kp, float* __restrict__ vp)
{
    extern __shared__ char smem[];
    const int tid  = threadIdx.x;
    const int lane = tid & 31;
    const int warp = tid >> 5;
    const int wm = (warp & 1) * 64;           // WRM=2
    const int wn = (warp >> 1) * 32;          // WRN=4
    const int bm = blockIdx.y * 128;
    const int bn = blockIdx.x * 128;
    const int niter = K / 32;

    float acc[4][4][4] = {};

    auto issue = [&](int s) {
        char* st = smem + (s % 3) * GH_STAGE;
        int k0 = s * 32;
        #pragma unroll
        for (int r = 0; r < 2; r++) {
            int ch = tid + r * 256;
            int row = ch >> 2, kq = ch & 3;
            cp_async16(st + row * 80 + kq * 16,
                       &A[(size_t)(bm + row) * K + k0 + kq * 8]);
            cp_async16(st + 10240 + row * 80 + kq * 16,
                       &Bt[(size_t)(bn + row) * K + k0 + kq * 8]);
        }
    };

    auto compute = [&](int buf) {
        const uint32_t* Ab = (const uint32_t*)(smem + buf * GH_STAGE);
        const uint32_t* Bb = (const uint32_t*)(smem + buf * GH_STAGE + 10240);
        #pragma unroll
        for (int kk = 0; kk < 2; kk++) {            // two k16 slices per BK=32
            int c0 = kk * 8 + (lane & 3);
            uint32_t af[4][4];
            #pragma unroll
            for (int i = 0; i < 4; i++) {
                const uint32_t* p = &Ab[(wm + i * 16 + (lane >> 2)) * 20 + c0];
                af[i][0] = p[0];
                af[i][1] = p[160];      // +8 rows * 20 words
                af[i][2] = p[4];        // +8 halves
                af[i][3] = p[164];
            }
            uint32_t bf[4][2];
            #pragma unroll
            for (int j = 0; j < 4; j++) {
                const uint32_t* p = &Bb[(wn + j * 8 + (lane >> 2)) * 20 + c0];
                bf[j][0] = p[0];
                bf[j][1] = p[4];        // k+8
            }
            #pragma unroll
            for (int i = 0; i < 4; i++)
                #pragma unroll
                for (int j = 0; j < 4; j++)
                    mma_f16(acc[i][j], af[i], bf[j]);
        }
    };

    #pragma unroll
    for (int s = 0; s < 2; s++) { if (s < niter) issue(s); cp_commit(); }
    for (int it = 0; it < niter; ++it) {
        cp_wait<1>();
        __syncthreads();
        if (it + 2 < niter) issue(it + 2);
        cp_commit();
        compute(it % 3);
    }

    // ---- epilogue ----
    #pragma unroll
    for (int i = 0; i < 4; i++) {
        #pragma unroll
        for (int j = 0; j < 4; j++) {
            int row = bm + wm + i * 16 + (lane >> 2);
            int col = bn + wn + j * 8 + (lane & 3) * 2;
            float2 bv = make_float2(0.f, 0.f);
            if (bias) bv = *(const float2*)&bias[col];
            float o[2][2] = {{acc[i][j][0] + bv.x, acc[i][j][1] + bv.y},
                             {acc[i][j][2] + bv.x, acc[i][j][3] + bv.y}};
            if (ACT == 0) {
                float* C = (float*)Cout;
                *(float2*)&C[(size_t)row * N + col]       = make_float2(o[0][0], o[0][1]);
                *(float2*)&C[(size_t)(row + 8) * N + col] = make_float2(o[1][0], o[1][1]);
            } else if (ACT == 1) {
                __half* C = (__half*)Cout;
                *(__half2*)&C[(size_t)row * N + col] =
                    __floats2half2_rn(gelu_exact(o[0][0]), gelu_exact(o[0][1]));
                *(__half2*)&C[(size_t)(row + 8) * N + col] =
                    __floats2half2_rn(gelu_exact(o[1][0]), gelu_exact(o[1][1]));
            } else {
                #pragma unroll
                for (int r = 0; r < 2; r++) {
                    int rr = row + r * 8;
                    int b = rr >> 9, s = rr & 511;
                    #pragma unroll
                    for (int cc = 0; cc < 2; cc++) {
                        int n = col + cc;
                        int c3 = n % 3, hd = n / 3;
                        int h = hd >> 6, d = hd & 63;
                        size_t idx = ((size_t)(b * H_ + h) * S_ + s) * D_ + d;
                        float val = f2tf32f(o[r][cc]);
                        if (c3 == 0) qp[idx] = val;
                        else if (c3 == 1) kp[idx] = val;
                        else vp[idx] = val;
                    }
                }
            }
        }
    }
}

// ---------------- fused attention (tf32 mma.sync, as R5) --------------------
#define FA_OFF_Q  33024
#define FA_OFF_K0 37376
#define FA_OFF_K1 46592
#define FA_SMEM   ((46592 + 9216) * 4)      // 223232 bytes

__global__ void __launch_bounds__(256, 1) flash_kernel(
    const float* __restrict__ q, const float* __restrict__ k,
    const float* __restrict__ v, __half* __restrict__ merged)
{
    extern __shared__ float fs[];
    float* Ssm = fs;                 // stride 516
    float* Qs  = fs + FA_OFF_Q;      // stride 68
    float* KVa = fs + FA_OFF_K0;     // K stride 68 / V stride 72
    float* KVb = fs + FA_OFF_K1;

    const int tid = threadIdx.x, lane = tid & 31, warp = tid >> 5;
    const int z = blockIdx.y;                 // b*H + h
    const int q0 = blockIdx.x * 64;
    const float* qg = q + (long long)z * S_ * D_ + (long long)q0 * D_;
    const float* kg = k + (long long)z * S_ * D_;
    const float* vg = v + (long long)z * S_ * D_;

    #pragma unroll
    for (int r = 0; r < 4; r++) {
        int chunk = tid + r * 256;
        int row = chunk >> 4, c4 = (chunk & 15) * 4;
        cp_async16(&Qs[row * 68 + c4], &qg[row * 64 + c4]);
    }
    #pragma unroll
    for (int r = 0; r < 8; r++) {
        int chunk = tid + r * 256;
        int row = chunk >> 4, c4 = (chunk & 15) * 4;
        cp_async16(&KVa[row * 68 + c4], &kg[row * 64 + c4]);
    }
    cp_commit();

    const int wm = (warp & 1) * 32;
    const int wn1 = (warp >> 1) * 32;

    // pass 1: S = Q @ K^T
    for (int j = 0; j < 4; j++) {
        cp_wait<0>();
        __syncthreads();
        if (j < 3) {
            float* dst = ((j + 1) & 1) ? KVb : KVa;
            const float* src = kg + (long long)(j + 1) * 128 * 64;
            #pragma unroll
            for (int r = 0; r < 8; r++) {
                int chunk = tid + r * 256;
                int row = chunk >> 4, c4 = (chunk & 15) * 4;
                cp_async16(&dst[row * 68 + c4], &src[row * 64 + c4]);
            }
            cp_commit();
        }
        const float* Kb = (j & 1) ? KVb : KVa;
        float acc[2][4][4] = {};
        #pragma unroll
        for (int kk = 0; kk < 8; kk++) {
            int c0 = kk * 8 + (lane & 3);
            uint32_t af[2][4];
            #pragma unroll
            for (int i = 0; i < 2; i++) {
                const uint32_t* p = (const uint32_t*)&Qs[(wm + i * 16 + (lane >> 2)) * 68 + c0];
                af[i][0] = p[0]; af[i][1] = p[8 * 68];
                af[i][2] = p[4]; af[i][3] = p[8 * 68 + 4];
            }
            uint32_t bf[4][2];
            #pragma unroll
            for (int jj = 0; jj < 4; jj++) {
                const uint32_t* p = (const uint32_t*)&Kb[(wn1 + jj * 8 + (lane >> 2)) * 68 + c0];
                bf[jj][0] = p[0]; bf[jj][1] = p[4];
            }
            #pragma unroll
            for (int i = 0; i < 2; i++)
                #pragma unroll
                for (int jj = 0; jj < 4; jj++)
                    mma_tf32(acc[i][jj], af[i], bf[jj]);
        }
        #pragma unroll
        for (int i = 0; i < 2; i++) {
            #pragma unroll
            for (int jj = 0; jj < 4; jj++) {
                int r = wm + i * 16 + (lane >> 2);
                int col = j * 128 + wn1 + jj * 8 + (lane & 3) * 2;
                *(float2*)&Ssm[r * 516 + col]       = make_float2(acc[i][jj][0], acc[i][jj][1]);
                *(float2*)&Ssm[(r + 8) * 516 + col] = make_float2(acc[i][jj][2], acc[i][jj][3]);
            }
        }
    }
    #pragma unroll
    for (int r = 0; r < 8; r++) {
        int chunk = tid + r * 256;
        int row = chunk >> 4, c4 = (chunk & 15) * 4;
        cp_async16(&KVa[row * 72 + c4], &vg[row * 64 + c4]);
    }
    cp_commit();
    __syncthreads();

    // pass 2: softmax + *1/sqrt(768) + tf32 round
    for (int rr = 0; rr < 8; rr++) {
        float* p = &Ssm[(warp * 8 + rr) * 516];
        float vals[16];
        float m = -INFINITY;
        #pragma unroll
        for (int i = 0; i < 16; i++) { vals[i] = p[lane + 32 * i]; m = fmaxf(m, vals[i]); }
        #pragma unroll
        for (int o = 16; o; o >>= 1) m = fmaxf(m, __shfl_xor_sync(0xffffffffu, m, o));
        float s = 0.f;
        #pragma unroll
        for (int i = 0; i < 16; i++) { vals[i] = expf(vals[i] - m); s += vals[i]; }
        #pragma unroll
        for (int o = 16; o; o >>= 1) s += __shfl_xor_sync(0xffffffffu, s, o);
        float inv = SCALE_INV / s;
        #pragma unroll
        for (int i = 0; i < 16; i++) p[lane + 32 * i] = f2tf32f(vals[i] * inv);
    }
    __syncthreads();

    // pass 3: O = P @ V
    const int wn3 = (warp >> 1) * 16;
    float acco[2][2][4] = {};
    for (int j = 0; j < 4; j++) {
        cp_wait<0>();
        __syncthreads();
        if (j < 3) {
            float* dst = ((j + 1) & 1) ? KVb : KVa;
            const float* src = vg + (long long)(j + 1) * 128 * 64;
            #pragma unroll
            for (int r = 0; r < 8; r++) {
                int chunk = tid + r * 256;
                int row = chunk >> 4, c4 = (chunk & 15) * 4;
                cp_async16(&dst[row * 72 + c4], &src[row * 64 + c4]);
            }
            cp_commit();
        }
        const float* Vb = (j & 1) ? KVb : KVa;
        #pragma unroll
        for (int kk = 0; kk < 16; kk++) {
            int c0 = j * 128 + kk * 8 + (lane & 3);
            uint32_t af[2][4];
            #pragma unroll
            for (int i = 0; i < 2; i++) {
                const uint32_t* p = (const uint32_t*)&Ssm[(wm + i * 16 + (lane >> 2)) * 516 + c0];
                af[i][0] = p[0]; af[i][1] = p[8 * 516];
                af[i][2] = p[4]; af[i][3] = p[8 * 516 + 4];
            }
            uint32_t bf[2][2];
            #pragma unroll
            for (int jj = 0; jj < 2; jj++) {
                const uint32_t* p = (const uint32_t*)&Vb[(kk * 8 + (lane & 3)) * 72
                                                        + wn3 + jj * 8 + (lane >> 2)];
                bf[jj][0] = p[0]; bf[jj][1] = p[4 * 72];
            }
            #pragma unroll
            for (int i = 0; i < 2; i++)
                #pragma unroll
                for (int jj = 0; jj < 2; jj++)
                    mma_tf32(acco[i][jj], af[i], bf[jj]);
        }
    }

    const int b = z / H_, h = z % H_;
    #pragma unroll
    for (int i = 0; i < 2; i++) {
        #pragma unroll
        for (int jj = 0; jj < 2; jj++) {
            int r = wm + i * 16 + (lane >> 2);
            int col = wn3 + jj * 8 + (lane & 3) * 2;
            long long s0 = b * S_ + q0 + r;
            *(__half2*)&merged[s0 * E_ + h * 64 + col] =
                __floats2half2_rn(acco[i][jj][0], acco[i][jj][1]);
            *(__half2*)&merged[(s0 + 8) * E_ + h * 64 + col] =
                __floats2half2_rn(acco[i][jj][2], acco[i][jj][3]);
        }
    }
}

// ---------------- reductions ----------------
__device__ __forceinline__ float block_reduce(float v) {
    __shared__ float sh[8];
    int lane = threadIdx.x & 31, wid = threadIdx.x >> 5;
    #pragma unroll
    for (int o = 16; o; o >>= 1) v += __shfl_xor_sync(0xffffffffu, v, o);
    if (lane == 0) sh[wid] = v;
    __syncthreads();
    if (wid == 0) {
        v = (lane < 8) ? sh[lane] : 0.0f;
        #pragma unroll
        for (int o = 4; o; o >>= 1) v += __shfl_xor_sync(0xffffffffu, v, o);
        if (lane == 0) sh[0] = v;
    }
    __syncthreads();
    float r = sh[0];
    __syncthreads();
    return r;
}

// ---------------- LN (standalone, half out) ----------------
__global__ __launch_bounds__(256) void ln_kernel(
    const float* __restrict__ in, const float* __restrict__ g,
    const float* __restrict__ bb, __half* __restrict__ out)
{
    long long base = (long long)blockIdx.x * E_;
    int t = threadIdx.x;
    float v[3];
    #pragma unroll
    for (int i = 0; i < 3; i++) v[i] = in[base + t + i*256];
    float s  = block_reduce(v[0] + v[1] + v[2]);
    float sq = block_reduce(v[0]*v[0] + v[1]*v[1] + v[2]*v[2]);
    float mean = s * (1.0f/E_);
    float rstd = rsqrtf(sq * (1.0f/E_) - mean*mean + 1e-5f);
    #pragma unroll
    for (int i = 0; i < 3; i++) {
        int c = t + i*256;
        out[base + c] = __float2half_rn((v[i] - mean) * rstd * g[c] + bb[c]);
    }
}

// ---------------- fused LN2(+x)->r1(f32) then LN3->f(half) ----------------
__global__ __launch_bounds__(256) void ln2_ln3_kernel(
    const float* __restrict__ oproj, const float* __restrict__ x,
    const float* __restrict__ g2, const float* __restrict__ b2,
    const float* __restrict__ g3, const float* __restrict__ b3,
    float* __restrict__ r1, __half* __restrict__ f)
{
    long long base = (long long)blockIdx.x * E_;
    int t = threadIdx.x;
    float v[3];
    #pragma unroll
    for (int i = 0; i < 3; i++) v[i] = oproj[base + t + i*256];
    float s  = block_reduce(v[0] + v[1] + v[2]);
    float sq = block_reduce(v[0]*v[0] + v[1]*v[1] + v[2]*v[2]);
    float mean = s * (1.0f/E_);
    float rstd = rsqrtf(sq * (1.0f/E_) - mean*mean + 1e-5f);
    #pragma unroll
    for (int i = 0; i < 3; i++) {
        int c = t + i*256;
        v[i] = (v[i] - mean) * rstd * g2[c] + b2[c] + x[base + c];
        r1[base + c] = v[i];
    }
    float s2  = block_reduce(v[0] + v[1] + v[2]);
    float sq2 = block_reduce(v[0]*v[0] + v[1]*v[1] + v[2]*v[2]);
    float mean2 = s2 * (1.0f/E_);
    float rstd2 = rsqrtf(sq2 * (1.0f/E_) - mean2*mean2 + 1e-5f);
    #pragma unroll
    for (int i = 0; i < 3; i++) {
        int c = t + i*256;
        f[base + c] = __float2half_rn((v[i] - mean2) * rstd2 * g3[c] + b3[c]);
    }
}

// ---------------- fused LN4(+r1+x)->x(f32) then LN1(next)->h(half) ----------
__global__ __launch_bounds__(256) void ln4_ln1_kernel(
    const float* __restrict__ f2, const float* __restrict__ r1,
    const float* __restrict__ x,
    const float* __restrict__ g4, const float* __restrict__ b4,
    const float* __restrict__ g1, const float* __restrict__ b1,
    float* __restrict__ xout, __half* __restrict__ hout)
{
    long long base = (long long)blockIdx.x * E_;
    int t = threadIdx.x;
    float v[3];
    #pragma unroll
    for (int i = 0; i < 3; i++) v[i] = f2[base + t + i*256];
    float s  = block_reduce(v[0] + v[1] + v[2]);
    float sq = block_reduce(v[0]*v[0] + v[1]*v[1] + v[2]*v[2]);
    float mean = s * (1.0f/E_);
    float rstd = rsqrtf(sq * (1.0f/E_) - mean*mean + 1e-5f);
    #pragma unroll
    for (int i = 0; i < 3; i++) {
        int c = t + i*256;
        v[i] = (v[i] - mean) * rstd * g4[c] + b4[c] + r1[base + c] + x[base + c];
        xout[base + c] = v[i];
    }
    if (g1 == nullptr) return;
    float s2  = block_reduce(v[0] + v[1] + v[2]);
    float sq2 = block_reduce(v[0]*v[0] + v[1]*v[1] + v[2]*v[2]);
    float mean2 = s2 * (1.0f/E_);
    float rstd2 = rsqrtf(sq2 * (1.0f/E_) - mean2*mean2 + 1e-5f);
    #pragma unroll
    for (int i = 0; i < 3; i++) {
        int c = t + i*256;
        hout[base + c] = __float2half_rn((v[i] - mean2) * rstd2 * g1[c] + b1[c]);
    }
}

// -------- weight transpose + halve: in [L][K][N] f32 -> out [L][N][K] half --
__global__ __launch_bounds__(256) void transpose_h(
    const float* __restrict__ in, __half* __restrict__ out, int K, int N)
{
    __shared__ float t[32][33];
    size_t lofs = (size_t)blockIdx.z * K * N;
    in += lofs; out += lofs;
    int n0 = blockIdx.x * 32, k0 = blockIdx.y * 32;
    int tx = threadIdx.x & 31, ty = threadIdx.x >> 5;   // 32 x 8
    #pragma unroll
    for (int i = 0; i < 4; i++)
        t[ty + i*8][tx] = in[(size_t)(k0 + ty + i*8) * N + n0 + tx];
    __syncthreads();
    #pragma unroll
    for (int i = 0; i < 4; i++)
        out[(size_t)(n0 + ty + i*8) * K + k0 + tx] = __float2half_rn(t[tx][ty + i*8]);
}

// ---------------- host orchestration ----------------
extern "C" void kernel_launch(void* const* d_in, const int* in_sizes, int n_in,
                              void* d_out, int out_size)
{
    (void)in_sizes; (void)n_in; (void)out_size;

    const float* x_in  = (const float*)d_in[0];
    const float* Wqkv  = (const float*)d_in[1];
    const float* bqkv  = (const float*)d_in[2];
    const float* Wp    = (const float*)d_in[3];
    const float* bp    = (const float*)d_in[4];
    const float* W1    = (const float*)d_in[5];
    const float* b1    = (const float*)d_in[6];
    const float* W2    = (const float*)d_in[7];
    const float* b2    = (const float*)d_in[8];
    const float* g1    = (const float*)d_in[9];
    const float* be1   = (const float*)d_in[10];
    const float* g2    = (const float*)d_in[11];
    const float* be2   = (const float*)d_in[12];
    const float* g3    = (const float*)d_in[13];
    const float* be3   = (const float*)d_in[14];
    const float* g4    = (const float*)d_in[15];
    const float* be4   = (const float*)d_in[16];

    static bool attr_done = false;
    if (!attr_done) {
        cudaFuncSetAttribute(gemm_h<0>,
                             cudaFuncAttributeMaxDynamicSharedMemorySize, GH_SMEM);
        cudaFuncSetAttribute(gemm_h<1>,
                             cudaFuncAttributeMaxDynamicSharedMemorySize, GH_SMEM);
        cudaFuncSetAttribute(gemm_h<2>,
                             cudaFuncAttributeMaxDynamicSharedMemorySize, GH_SMEM);
        cudaFuncSetAttribute(flash_kernel,
                             cudaFuncAttributeMaxDynamicSharedMemorySize, FA_SMEM);
        attr_done = true;
    }

    __half *p_h, *p_merged, *p_f, *p_ff;
    float *p_q, *p_k, *p_v, *p_oproj, *p_r1, *p_f2, *p_x;
    __half *w_qkv, *w_p, *w_1, *w_2;
    cudaGetSymbolAddress((void**)&p_h, g_h);
    cudaGetSymbolAddress((void**)&p_q, g_q);
    cudaGetSymbolAddress((void**)&p_k, g_k);
    cudaGetSymbolAddress((void**)&p_v, g_v);
    cudaGetSymbolAddress((void**)&p_merged, g_merged);
    cudaGetSymbolAddress((void**)&p_oproj, g_oproj);
    cudaGetSymbolAddress((void**)&p_r1, g_r1);
    cudaGetSymbolAddress((void**)&p_f, g_f);
    cudaGetSymbolAddress((void**)&p_ff, g_ff);
    cudaGetSymbolAddress((void**)&p_f2, g_f2);
    cudaGetSymbolAddress((void**)&p_x, g_x);
    cudaGetSymbolAddress((void**)&w_qkv, g_Wqkv_t);
    cudaGetSymbolAddress((void**)&w_p, g_Wp_t);
    cudaGetSymbolAddress((void**)&w_1, g_W1_t);
    cudaGetSymbolAddress((void**)&w_2, g_W2_t);

    // pre-transpose + halve all weights (once per launch)
    transpose_h<<<dim3(E3_/32, E_/32, L_), 256>>>(Wqkv, w_qkv, E_, E3_);
    transpose_h<<<dim3(E_/32,  E_/32, L_), 256>>>(Wp,   w_p,   E_, E_);
    transpose_h<<<dim3(FF_/32, E_/32, L_), 256>>>(W1,   w_1,   E_, FF_);
    transpose_h<<<dim3(E_/32, FF_/32, L_), 256>>>(W2,   w_2,   FF_, E_);

    cudaMemcpyAsync(p_x, x_in, (size_t)NTOK * E_ * sizeof(float),
                    cudaMemcpyDeviceToDevice, 0);

    // h = LN1_0(x)
    ln_kernel<<<NTOK, 256>>>(p_x, g1, be1, p_h);

    for (int l = 0; l < L_; ++l) {
        const __half* Wqkv_l = w_qkv + (size_t)l * E_ * E3_;
        const float*  bqkv_l = bqkv + (size_t)l * E3_;
        const __half* Wp_l   = w_p  + (size_t)l * E_ * E_;
        const float*  bp_l   = bp   + (size_t)l * E_;
        const __half* W1_l   = w_1  + (size_t)l * E_ * FF_;
        const float*  b1_l   = b1   + (size_t)l * FF_;
        const __half* W2_l   = w_2  + (size_t)l * FF_ * E_;
        const float*  b2_l   = b2   + (size_t)l * E_;
        const float* g2_l = g2 + (size_t)l * E_, *be2_l = be2 + (size_t)l * E_;
        const float* g3_l = g3 + (size_t)l * E_, *be3_l = be3 + (size_t)l * E_;
        const float* g4_l = g4 + (size_t)l * E_, *be4_l = be4 + (size_t)l * E_;

        // qkv = h @ Wqkv + bqkv -> split q,k,v (f32, tf32-rounded)
        gemm_h<2><<<dim3(E3_/128, NTOK/128), 256, GH_SMEM>>>(
            p_h, Wqkv_l, bqkv_l, nullptr, NTOK, E3_, E_, p_q, p_k, p_v);
        // fused attention -> merged (half)
        flash_kernel<<<dim3(S_/64, BH), 256, FA_SMEM>>>(p_q, p_k, p_v, p_merged);
        // oproj = merged @ Wp + bp (f32)
        gemm_h<0><<<dim3(E_/128, NTOK/128), 256, GH_SMEM>>>(
            p_merged, Wp_l, bp_l, p_oproj, NTOK, E_, E_, nullptr, nullptr, nullptr);
        // r1 = LN2(oproj) + x ; f = LN3(r1) (half)
        ln2_ln3_kernel<<<NTOK, 256>>>(p_oproj, p_x, g2_l, be2_l, g3_l, be3_l, p_r1, p_f);
        // ff = gelu(f @ W1 + b1) (half)
        gemm_h<1><<<dim3(FF_/128, NTOK/128), 256, GH_SMEM>>>(
            p_f, W1_l, b1_l, p_ff, NTOK, FF_, E_, nullptr, nullptr, nullptr);
        // f2 = ff @ W2 + b2 (f32)
        gemm_h<0><<<dim3(E_/128, NTOK/128), 256, GH_SMEM>>>(
            p_ff, W2_l, b2_l, p_f2, NTOK, E_, FF_, nullptr, nullptr, nullptr);
        // x = LN4(f2) + r1 + x ; h = LN1_{l+1}(x) (half)
        const float* g1n  = (l + 1 < L_) ? g1  + (size_t)(l + 1) * E_ : nullptr;
        const float* be1n = (l + 1 < L_) ? be1 + (size_t)(l + 1) * E_ : nullptr;
        ln4_ln1_kernel<<<NTOK, 256>>>(p_f2, p_r1, p_x, g4_l, be4_l, g1n, be1n, p_x, p_h);
    }

    cudaMemcpyAsync(d_out, p_x, (size_t)NTOK * E_ * sizeof(float),
                    cudaMemcpyDeviceToDevice, 0);
}

// round 9
// speedup vs baseline: 1.7748x; 1.1164x over previous
#include <cuda_runtime.h>
#include <cuda_fp16.h>
#include <math.h>
#include <stdint.h>

#define B_   4
#define S_   512
#define E_   768
#define H_   12
#define D_   64
#define FF_  3072
#define L_   12
#define NTOK (B_*S_)     // 2048
#define BH   (B_*H_)     // 48
#define E3_  (3*E_)      // 2304

#define SCALE_INV 0.03608439182435161f   // 1/sqrt(768), applied AFTER softmax

// ---------------- scratch (static __device__, no allocation) ----------------
__device__ __half g_h[NTOK*E_];
__device__ __half g_q[BH*S_*D_];        // [z][s][d]
__device__ __half g_k[BH*S_*D_];        // [z][s][d]
__device__ __half g_v[BH*D_*S_];        // [z][d][s]  (transposed for PV)
__device__ __half g_merged[NTOK*E_];
__device__ float  g_oproj[NTOK*E_];
__device__ float  g_r1[NTOK*E_];
__device__ __half g_f[NTOK*E_];
__device__ __half g_ff[NTOK*FF_];
__device__ float  g_f2[NTOK*E_];
__device__ float  g_x[NTOK*E_];
// fp16 + transposed weight copies ([N][K] K-major per layer)
__device__ __half g_Wqkv_t[(size_t)L_*E_*E3_];
__device__ __half g_Wp_t[(size_t)L_*E_*E_];
__device__ __half g_W1_t[(size_t)L_*E_*FF_];
__device__ __half g_W2_t[(size_t)L_*FF_*E_];

// ---------------- helpers ----------------
__device__ __forceinline__ void mma_f16(float* c, const uint32_t* a, const uint32_t* b) {
    asm volatile(
        "mma.sync.aligned.m16n8k16.row.col.f32.f16.f16.f32 "
        "{%0,%1,%2,%3}, {%4,%5,%6,%7}, {%8,%9}, {%0,%1,%2,%3};"
        : "+f"(c[0]), "+f"(c[1]), "+f"(c[2]), "+f"(c[3])
        : "r"(a[0]), "r"(a[1]), "r"(a[2]), "r"(a[3]), "r"(b[0]), "r"(b[1]));
}

__device__ __forceinline__ void cp_async16(void* smem, const void* gmem) {
    uint32_t s = (uint32_t)__cvta_generic_to_shared(smem);
    asm volatile("cp.async.cg.shared.global [%0], [%1], 16;\n" :: "r"(s), "l"(gmem));
}
__device__ __forceinline__ void cp_commit() {
    asm volatile("cp.async.commit_group;\n");
}
template<int N> __device__ __forceinline__ void cp_wait() {
    asm volatile("cp.async.wait_group %0;\n" :: "n"(N));
}

__device__ __forceinline__ float gelu_exact(float x) {
    return 0.5f * x * (1.0f + erff(x * 0.7071067811865476f));
}

// ---------------- fp16 tensor-core GEMM, cp.async 3-stage -------------------
// C = A[M,K](half) @ Bt[N,K](half, pre-transposed) + bias(f32).
// ACT: 0 plain f32 out; 1 gelu -> half out; 2 qkv-split scatter (half).
#define GH_STAGE 20480                       // 10240 A + 10240 B
#define GH_SMEM  (3 * GH_STAGE)              // 61440

template<int ACT>
__global__ void __launch_bounds__(256, 2) gemm_h(
    const __half* __restrict__ A, const __half* __restrict__ Bt,
    const float* __restrict__ bias, void* __restrict__ Cout,
    int M, int N, int K,
    __half* __restrict__ qp, __half* __restrict__ kp, __half* __restrict__ vp)
{
    extern __shared__ char smem[];
    const int tid  = threadIdx.x;
    const int lane = tid & 31;
    const int warp = tid >> 5;
    const int wm = (warp & 1) * 64;           // WRM=2
    const int wn = (warp >> 1) * 32;          // WRN=4
    const int bm = blockIdx.y * 128;
    const int bn = blockIdx.x * 128;
    const int niter = K / 32;

    float acc[4][4][4] = {};

    auto issue = [&](int s) {
        char* st = smem + (s % 3) * GH_STAGE;
        int k0 = s * 32;
        #pragma unroll
        for (int r = 0; r < 2; r++) {
            int ch = tid + r * 256;
            int row = ch >> 2, kq = ch & 3;
            cp_async16(st + row * 80 + kq * 16,
                       &A[(size_t)(bm + row) * K + k0 + kq * 8]);
            cp_async16(st + 10240 + row * 80 + kq * 16,
                       &Bt[(size_t)(bn + row) * K + k0 + kq * 8]);
        }
    };

    auto compute = [&](int buf) {
        const uint32_t* Ab = (const uint32_t*)(smem + buf * GH_STAGE);
        const uint32_t* Bb = (const uint32_t*)(smem + buf * GH_STAGE + 10240);
        #pragma unroll
        for (int kk = 0; kk < 2; kk++) {
            int c0 = kk * 8 + (lane & 3);
            uint32_t af[4][4];
            #pragma unroll
            for (int i = 0; i < 4; i++) {
                const uint32_t* p = &Ab[(wm + i * 16 + (lane >> 2)) * 20 + c0];
                af[i][0] = p[0];
                af[i][1] = p[160];
                af[i][2] = p[4];
                af[i][3] = p[164];
            }
            uint32_t bf[4][2];
            #pragma unroll
            for (int j = 0; j < 4; j++) {
                const uint32_t* p = &Bb[(wn + j * 8 + (lane >> 2)) * 20 + c0];
                bf[j][0] = p[0];
                bf[j][1] = p[4];
            }
            #pragma unroll
            for (int i = 0; i < 4; i++)
                #pragma unroll
                for (int j = 0; j < 4; j++)
                    mma_f16(acc[i][j], af[i], bf[j]);
        }
    };

    #pragma unroll
    for (int s = 0; s < 2; s++) { if (s < niter) issue(s); cp_commit(); }
    for (int it = 0; it < niter; ++it) {
        cp_wait<1>();
        __syncthreads();
        if (it + 2 < niter) issue(it + 2);
        cp_commit();
        compute(it % 3);
    }

    // ---- epilogue ----
    #pragma unroll
    for (int i = 0; i < 4; i++) {
        #pragma unroll
        for (int j = 0; j < 4; j++) {
            int row = bm + wm + i * 16 + (lane >> 2);
            int col = bn + wn + j * 8 + (lane & 3) * 2;
            float2 bv = make_float2(0.f, 0.f);
            if (bias) bv = *(const float2*)&bias[col];
            float o[2][2] = {{acc[i][j][0] + bv.x, acc[i][j][1] + bv.y},
                             {acc[i][j][2] + bv.x, acc[i][j][3] + bv.y}};
            if (ACT == 0) {
                float* C = (float*)Cout;
                *(float2*)&C[(size_t)row * N + col]       = make_float2(o[0][0], o[0][1]);
                *(float2*)&C[(size_t)(row + 8) * N + col] = make_float2(o[1][0], o[1][1]);
            } else if (ACT == 1) {
                __half* C = (__half*)Cout;
                *(__half2*)&C[(size_t)row * N + col] =
                    __floats2half2_rn(gelu_exact(o[0][0]), gelu_exact(o[0][1]));
                *(__half2*)&C[(size_t)(row + 8) * N + col] =
                    __floats2half2_rn(gelu_exact(o[1][0]), gelu_exact(o[1][1]));
            } else {
                #pragma unroll
                for (int r = 0; r < 2; r++) {
                    int rr = row + r * 8;
                    int b = rr >> 9, s = rr & 511;
                    #pragma unroll
                    for (int cc = 0; cc < 2; cc++) {
                        int n = col + cc;
                        int c3 = n % 3, hd = n / 3;
                        int h = hd >> 6, d = hd & 63;
                        int z = b * H_ + h;
                        __half val = __float2half_rn(o[r][cc]);
                        if (c3 == 0)      qp[((size_t)z * S_ + s) * D_ + d] = val;
                        else if (c3 == 1) kp[((size_t)z * S_ + s) * D_ + d] = val;
                        else              vp[((size_t)z * D_ + d) * S_ + s] = val;
                    }
                }
            }
        }
    }
}

// ---------------- flash attention v2: online softmax, fp16 MMA --------------
// CTA: 64 query rows x one (b,h). 128 threads; warp w owns rows w*16..w*16+15.
// q,k: [z][s][64] half; v: [z][64][s] half (transposed). merged: half.
#define FA2_SMEM 64512     // Q 9216 + 3*K 27648 + 3*V 27648 bytes

__global__ void __launch_bounds__(128, 2) flash2_kernel(
    const __half* __restrict__ q, const __half* __restrict__ k,
    const __half* __restrict__ vt, __half* __restrict__ merged)
{
    extern __shared__ __half hs[];
    __half* Qs = hs;                     // 64 x 72
    __half* Ks = hs + 4608;              // 3 x (64 x 72)
    __half* Vs = hs + 4 * 4608;          // 3 x (64 x 72)

    const int tid = threadIdx.x, lane = tid & 31, warp = tid >> 5;
    const int z = blockIdx.y, q0 = blockIdx.x * 64;
    const __half* qg = q  + (size_t)z * S_ * D_ + (size_t)q0 * D_;
    const __half* kg = k  + (size_t)z * S_ * D_;
    const __half* vg = vt + (size_t)z * D_ * S_;

    auto loadKV = [&](int t) {
        __half* dk = Ks + (t % 3) * 4608;
        __half* dv = Vs + (t % 3) * 4608;
        const __half* sk = kg + (size_t)t * 64 * 64;
        #pragma unroll
        for (int r = 0; r < 4; r++) {
            int ch = tid + r * 128;
            int row = ch >> 3, c = ch & 7;
            cp_async16(dk + row * 72 + c * 8, sk + row * 64 + c * 8);
            cp_async16(dv + row * 72 + c * 8, vg + row * 512 + t * 64 + c * 8);
        }
    };

    #pragma unroll
    for (int r = 0; r < 4; r++) {
        int ch = tid + r * 128;
        int row = ch >> 3, c = ch & 7;
        cp_async16(Qs + row * 72 + c * 8, qg + row * 64 + c * 8);
    }
    loadKV(0); cp_commit();
    loadKV(1); cp_commit();

    uint32_t qa[4][4];
    float Oacc[8][4] = {};
    float m0 = -INFINITY, m1 = -INFINITY, l0 = 0.f, l1 = 0.f;

    const int r0 = warp * 16 + (lane >> 2);
    const int ccol = (lane & 3) * 2;

    for (int t = 0; t < 8; t++) {
        cp_wait<1>();
        __syncthreads();
        if (t == 0) {
            #pragma unroll
            for (int kc = 0; kc < 4; kc++) {
                qa[kc][0] = *(const uint32_t*)(Qs + r0 * 72 + kc * 16 + ccol);
                qa[kc][1] = *(const uint32_t*)(Qs + (r0 + 8) * 72 + kc * 16 + ccol);
                qa[kc][2] = *(const uint32_t*)(Qs + r0 * 72 + kc * 16 + 8 + ccol);
                qa[kc][3] = *(const uint32_t*)(Qs + (r0 + 8) * 72 + kc * 16 + 8 + ccol);
            }
        }
        if (t + 2 < 8) loadKV(t + 2);
        cp_commit();

        const __half* Kt = Ks + (t % 3) * 4608;
        const __half* Vb = Vs + (t % 3) * 4608;

        // S = Q @ K^T (16 rows x 64 keys per warp)
        float sacc[8][4] = {};
        #pragma unroll
        for (int kc = 0; kc < 4; kc++) {
            uint32_t kb[8][2];
            #pragma unroll
            for (int nt = 0; nt < 8; nt++) {
                const __half* pk = Kt + (nt * 8 + (lane >> 2)) * 72 + kc * 16 + ccol;
                kb[nt][0] = *(const uint32_t*)pk;
                kb[nt][1] = *(const uint32_t*)(pk + 8);
            }
            #pragma unroll
            for (int nt = 0; nt < 8; nt++)
                mma_f16(sacc[nt], qa[kc], kb[nt]);
        }

        // online softmax update (rows r0 / r0+8 live in lane quads)
        float mt0 = -INFINITY, mt1 = -INFINITY;
        #pragma unroll
        for (int nt = 0; nt < 8; nt++) {
            mt0 = fmaxf(mt0, fmaxf(sacc[nt][0], sacc[nt][1]));
            mt1 = fmaxf(mt1, fmaxf(sacc[nt][2], sacc[nt][3]));
        }
        mt0 = fmaxf(mt0, __shfl_xor_sync(~0u, mt0, 1));
        mt0 = fmaxf(mt0, __shfl_xor_sync(~0u, mt0, 2));
        mt1 = fmaxf(mt1, __shfl_xor_sync(~0u, mt1, 1));
        mt1 = fmaxf(mt1, __shfl_xor_sync(~0u, mt1, 2));
        float mn0 = fmaxf(m0, mt0), mn1 = fmaxf(m1, mt1);
        float sc0 = expf(m0 - mn0), sc1 = expf(m1 - mn1);
        m0 = mn0; m1 = mn1;

        float ts0 = 0.f, ts1 = 0.f;
        uint32_t ph[8][2];
        #pragma unroll
        for (int nt = 0; nt < 8; nt++) {
            float p0 = expf(sacc[nt][0] - mn0), p1 = expf(sacc[nt][1] - mn0);
            float p2 = expf(sacc[nt][2] - mn1), p3 = expf(sacc[nt][3] - mn1);
            ts0 += p0 + p1; ts1 += p2 + p3;
            __half2 h0 = __floats2half2_rn(p0, p1);
            __half2 h1 = __floats2half2_rn(p2, p3);
            ph[nt][0] = *(uint32_t*)&h0;
            ph[nt][1] = *(uint32_t*)&h1;
        }
        ts0 += __shfl_xor_sync(~0u, ts0, 1); ts0 += __shfl_xor_sync(~0u, ts0, 2);
        ts1 += __shfl_xor_sync(~0u, ts1, 1); ts1 += __shfl_xor_sync(~0u, ts1, 2);
        l0 = l0 * sc0 + ts0;
        l1 = l1 * sc1 + ts1;
        #pragma unroll
        for (int nt = 0; nt < 8; nt++) {
            Oacc[nt][0] *= sc0; Oacc[nt][1] *= sc0;
            Oacc[nt][2] *= sc1; Oacc[nt][3] *= sc1;
        }

        // O += P @ V   (P C-fragment == A-fragment layout)
        #pragma unroll
        for (int kc = 0; kc < 4; kc++) {
            uint32_t vb[8][2];
            #pragma unroll
            for (int nt = 0; nt < 8; nt++) {
                const __half* pv = Vb + (nt * 8 + (lane >> 2)) * 72 + kc * 16 + ccol;
                vb[nt][0] = *(const uint32_t*)pv;
                vb[nt][1] = *(const uint32_t*)(pv + 8);
            }
            uint32_t af[4] = {ph[2*kc][0], ph[2*kc][1], ph[2*kc+1][0], ph[2*kc+1][1]};
            #pragma unroll
            for (int nt = 0; nt < 8; nt++)
                mma_f16(Oacc[nt], af, vb[nt]);
        }
    }

    const int b = z / H_, h = z % H_;
    float inv0 = SCALE_INV / l0, inv1 = SCALE_INV / l1;
    size_t s0 = (size_t)(b * S_ + q0 + r0) * E_ + h * 64 + ccol;
    size_t s1 = (size_t)(b * S_ + q0 + r0 + 8) * E_ + h * 64 + ccol;
    #pragma unroll
    for (int nt = 0; nt < 8; nt++) {
        *(__half2*)&merged[s0 + nt * 8] =
            __floats2half2_rn(Oacc[nt][0] * inv0, Oacc[nt][1] * inv0);
        *(__half2*)&merged[s1 + nt * 8] =
            __floats2half2_rn(Oacc[nt][2] * inv1, Oacc[nt][3] * inv1);
    }
}

// ---------------- reductions ----------------
__device__ __forceinline__ float block_reduce(float v) {
    __shared__ float sh[8];
    int lane = threadIdx.x & 31, wid = threadIdx.x >> 5;
    #pragma unroll
    for (int o = 16; o; o >>= 1) v += __shfl_xor_sync(0xffffffffu, v, o);
    if (lane == 0) sh[wid] = v;
    __syncthreads();
    if (wid == 0) {
        v = (lane < 8) ? sh[lane] : 0.0f;
        #pragma unroll
        for (int o = 4; o; o >>= 1) v += __shfl_xor_sync(0xffffffffu, v, o);
        if (lane == 0) sh[0] = v;
    }
    __syncthreads();
    float r = sh[0];
    __syncthreads();
    return r;
}

// ---------------- LN (standalone, half out) ----------------
__global__ __launch_bounds__(256) void ln_kernel(
    const float* __restrict__ in, const float* __restrict__ g,
    const float* __restrict__ bb, __half* __restrict__ out)
{
    long long base = (long long)blockIdx.x * E_;
    int t = threadIdx.x;
    float v[3];
    #pragma unroll
    for (int i = 0; i < 3; i++) v[i] = in[base + t + i*256];
    float s  = block_reduce(v[0] + v[1] + v[2]);
    float sq = block_reduce(v[0]*v[0] + v[1]*v[1] + v[2]*v[2]);
    float mean = s * (1.0f/E_);
    float rstd = rsqrtf(sq * (1.0f/E_) - mean*mean + 1e-5f);
    #pragma unroll
    for (int i = 0; i < 3; i++) {
        int c = t + i*256;
        out[base + c] = __float2half_rn((v[i] - mean) * rstd * g[c] + bb[c]);
    }
}

// ---------------- fused LN2(+x)->r1(f32) then LN3->f(half) ----------------
__global__ __launch_bounds__(256) void ln2_ln3_kernel(
    const float* __restrict__ oproj, const float* __restrict__ x,
    const float* __restrict__ g2, const float* __restrict__ b2,
    const float* __restrict__ g3, const float* __restrict__ b3,
    float* __restrict__ r1, __half* __restrict__ f)
{
    long long base = (long long)blockIdx.x * E_;
    int t = threadIdx.x;
    float v[3];
    #pragma unroll
    for (int i = 0; i < 3; i++) v[i] = oproj[base + t + i*256];
    float s  = block_reduce(v[0] + v[1] + v[2]);
    float sq = block_reduce(v[0]*v[0] + v[1]*v[1] + v[2]*v[2]);
    float mean = s * (1.0f/E_);
    float rstd = rsqrtf(sq * (1.0f/E_) - mean*mean + 1e-5f);
    #pragma unroll
    for (int i = 0; i < 3; i++) {
        int c = t + i*256;
        v[i] = (v[i] - mean) * rstd * g2[c] + b2[c] + x[base + c];
        r1[base + c] = v[i];
    }
    float s2  = block_reduce(v[0] + v[1] + v[2]);
    float sq2 = block_reduce(v[0]*v[0] + v[1]*v[1] + v[2]*v[2]);
    float mean2 = s2 * (1.0f/E_);
    float rstd2 = rsqrtf(sq2 * (1.0f/E_) - mean2*mean2 + 1e-5f);
    #pragma unroll
    for (int i = 0; i < 3; i++) {
        int c = t + i*256;
        f[base + c] = __float2half_rn((v[i] - mean2) * rstd2 * g3[c] + b3[c]);
    }
}

// ---------------- fused LN4(+r1+x)->x(f32) then LN1(next)->h(half) ----------
__global__ __launch_bounds__(256) void ln4_ln1_kernel(
    const float* __restrict__ f2, const float* __restrict__ r1,
    const float* __restrict__ x,
    const float* __restrict__ g4, const float* __restrict__ b4,
    const float* __restrict__ g1, const float* __restrict__ b1,
    float* __restrict__ xout, __half* __restrict__ hout)
{
    long long base = (long long)blockIdx.x * E_;
    int t = threadIdx.x;
    float v[3];
    #pragma unroll
    for (int i = 0; i < 3; i++) v[i] = f2[base + t + i*256];
    float s  = block_reduce(v[0] + v[1] + v[2]);
    float sq = block_reduce(v[0]*v[0] + v[1]*v[1] + v[2]*v[2]);
    float mean = s * (1.0f/E_);
    float rstd = rsqrtf(sq * (1.0f/E_) - mean*mean + 1e-5f);
    #pragma unroll
    for (int i = 0; i < 3; i++) {
        int c = t + i*256;
        v[i] = (v[i] - mean) * rstd * g4[c] + b4[c] + r1[base + c] + x[base + c];
        xout[base + c] = v[i];
    }
    if (g1 == nullptr) return;
    float s2  = block_reduce(v[0] + v[1] + v[2]);
    float sq2 = block_reduce(v[0]*v[0] + v[1]*v[1] + v[2]*v[2]);
    float mean2 = s2 * (1.0f/E_);
    float rstd2 = rsqrtf(sq2 * (1.0f/E_) - mean2*mean2 + 1e-5f);
    #pragma unroll
    for (int i = 0; i < 3; i++) {
        int c = t + i*256;
        hout[base + c] = __float2half_rn((v[i] - mean2) * rstd2 * g1[c] + b1[c]);
    }
}

// -------- weight transpose + halve: in [L][K][N] f32 -> out [L][N][K] half --
__global__ __launch_bounds__(256) void transpose_h(
    const float* __restrict__ in, __half* __restrict__ out, int K, int N)
{
    __shared__ float t[32][33];
    size_t lofs = (size_t)blockIdx.z * K * N;
    in += lofs; out += lofs;
    int n0 = blockIdx.x * 32, k0 = blockIdx.y * 32;
    int tx = threadIdx.x & 31, ty = threadIdx.x >> 5;   // 32 x 8
    #pragma unroll
    for (int i = 0; i < 4; i++)
        t[ty + i*8][tx] = in[(size_t)(k0 + ty + i*8) * N + n0 + tx];
    __syncthreads();
    #pragma unroll
    for (int i = 0; i < 4; i++)
        out[(size_t)(n0 + ty + i*8) * K + k0 + tx] = __float2half_rn(t[tx][ty + i*8]);
}

// ---------------- host orchestration ----------------
extern "C" void kernel_launch(void* const* d_in, const int* in_sizes, int n_in,
                              void* d_out, int out_size)
{
    (void)in_sizes; (void)n_in; (void)out_size;

    const float* x_in  = (const float*)d_in[0];
    const float* Wqkv  = (const float*)d_in[1];
    const float* bqkv  = (const float*)d_in[2];
    const float* Wp    = (const float*)d_in[3];
    const float* bp    = (const float*)d_in[4];
    const float* W1    = (const float*)d_in[5];
    const float* b1    = (const float*)d_in[6];
    const float* W2    = (const float*)d_in[7];
    const float* b2    = (const float*)d_in[8];
    const float* g1    = (const float*)d_in[9];
    const float* be1   = (const float*)d_in[10];
    const float* g2    = (const float*)d_in[11];
    const float* be2   = (const float*)d_in[12];
    const float* g3    = (const float*)d_in[13];
    const float* be3   = (const float*)d_in[14];
    const float* g4    = (const float*)d_in[15];
    const float* be4   = (const float*)d_in[16];

    static bool attr_done = false;
    if (!attr_done) {
        cudaFuncSetAttribute(gemm_h<0>,
                             cudaFuncAttributeMaxDynamicSharedMemorySize, GH_SMEM);
        cudaFuncSetAttribute(gemm_h<1>,
                             cudaFuncAttributeMaxDynamicSharedMemorySize, GH_SMEM);
        cudaFuncSetAttribute(gemm_h<2>,
                             cudaFuncAttributeMaxDynamicSharedMemorySize, GH_SMEM);
        cudaFuncSetAttribute(flash2_kernel,
                             cudaFuncAttributeMaxDynamicSharedMemorySize, FA2_SMEM);
        attr_done = true;
    }

    __half *p_h, *p_q, *p_k, *p_v, *p_merged, *p_f, *p_ff;
    float *p_oproj, *p_r1, *p_f2, *p_x;
    __half *w_qkv, *w_p, *w_1, *w_2;
    cudaGetSymbolAddress((void**)&p_h, g_h);
    cudaGetSymbolAddress((void**)&p_q, g_q);
    cudaGetSymbolAddress((void**)&p_k, g_k);
    cudaGetSymbolAddress((void**)&p_v, g_v);
    cudaGetSymbolAddress((void**)&p_merged, g_merged);
    cudaGetSymbolAddress((void**)&p_oproj, g_oproj);
    cudaGetSymbolAddress((void**)&p_r1, g_r1);
    cudaGetSymbolAddress((void**)&p_f, g_f);
    cudaGetSymbolAddress((void**)&p_ff, g_ff);
    cudaGetSymbolAddress((void**)&p_f2, g_f2);
    cudaGetSymbolAddress((void**)&p_x, g_x);
    cudaGetSymbolAddress((void**)&w_qkv, g_Wqkv_t);
    cudaGetSymbolAddress((void**)&w_p, g_Wp_t);
    cudaGetSymbolAddress((void**)&w_1, g_W1_t);
    cudaGetSymbolAddress((void**)&w_2, g_W2_t);

    // pre-transpose + halve all weights (once per launch)
    transpose_h<<<dim3(E3_/32, E_/32, L_), 256>>>(Wqkv, w_qkv, E_, E3_);
    transpose_h<<<dim3(E_/32,  E_/32, L_), 256>>>(Wp,   w_p,   E_, E_);
    transpose_h<<<dim3(FF_/32, E_/32, L_), 256>>>(W1,   w_1,   E_, FF_);
    transpose_h<<<dim3(E_/32, FF_/32, L_), 256>>>(W2,   w_2,   FF_, E_);

    cudaMemcpyAsync(p_x, x_in, (size_t)NTOK * E_ * sizeof(float),
                    cudaMemcpyDeviceToDevice, 0);

    // h = LN1_0(x)
    ln_kernel<<<NTOK, 256>>>(p_x, g1, be1, p_h);

    for (int l = 0; l < L_; ++l) {
        const __half* Wqkv_l = w_qkv + (size_t)l * E_ * E3_;
        const float*  bqkv_l = bqkv + (size_t)l * E3_;
        const __half* Wp_l   = w_p  + (size_t)l * E_ * E_;
        const float*  bp_l   = bp   + (size_t)l * E_;
        const __half* W1_l   = w_1  + (size_t)l * E_ * FF_;
        const float*  b1_l   = b1   + (size_t)l * FF_;
        const __half* W2_l   = w_2  + (size_t)l * FF_ * E_;
        const float*  b2_l   = b2   + (size_t)l * E_;
        const float* g2_l = g2 + (size_t)l * E_, *be2_l = be2 + (size_t)l * E_;
        const float* g3_l = g3 + (size_t)l * E_, *be3_l = be3 + (size_t)l * E_;
        const float* g4_l = g4 + (size_t)l * E_, *be4_l = be4 + (size_t)l * E_;

        // qkv = h @ Wqkv + bqkv -> split q,k (row-major) + v (transposed), half
        gemm_h<2><<<dim3(E3_/128, NTOK/128), 256, GH_SMEM>>>(
            p_h, Wqkv_l, bqkv_l, nullptr, NTOK, E3_, E_, p_q, p_k, p_v);
        // fused flash attention (online softmax) -> merged (half)
        flash2_kernel<<<dim3(S_/64, BH), 128, FA2_SMEM>>>(p_q, p_k, p_v, p_merged);
        // oproj = merged @ Wp + bp (f32)
        gemm_h<0><<<dim3(E_/128, NTOK/128), 256, GH_SMEM>>>(
            p_merged, Wp_l, bp_l, p_oproj, NTOK, E_, E_, nullptr, nullptr, nullptr);
        // r1 = LN2(oproj) + x ; f = LN3(r1) (half)
        ln2_ln3_kernel<<<NTOK, 256>>>(p_oproj, p_x, g2_l, be2_l, g3_l, be3_l, p_r1, p_f);
        // ff = gelu(f @ W1 + b1) (half)
        gemm_h<1><<<dim3(FF_/128, NTOK/128), 256, GH_SMEM>>>(
            p_f, W1_l, b1_l, p_ff, NTOK, FF_, E_, nullptr, nullptr, nullptr);
        // f2 = ff @ W2 + b2 (f32)
        gemm_h<0><<<dim3(E_/128, NTOK/128), 256, GH_SMEM>>>(
            p_ff, W2_l, b2_l, p_f2, NTOK, E_, FF_, nullptr, nullptr, nullptr);
        // x = LN4(f2) + r1 + x ; h = LN1_{l+1}(x) (half)
        const float* g1n  = (l + 1 < L_) ? g1  + (size_t)(l + 1) * E_ : nullptr;
        const float* be1n = (l + 1 < L_) ? be1 + (size_t)(l + 1) * E_ : nullptr;
        ln4_ln1_kernel<<<NTOK, 256>>>(p_f2, p_r1, p_x, g4_l, be4_l, g1n, be1n, p_x, p_h);
    }

    cudaMemcpyAsync(d_out, p_x, (size_t)NTOK * E_ * sizeof(float),
                    cudaMemcpyDeviceToDevice, 0);
}